// round 13
// baseline (speedup 1.0000x reference)
#include <cuda_runtime.h>
#include <math.h>
#include <stdint.h>

#define N_NODES 100000
#define N_EDGES 1600000
#define N_GRAPH 64
#define HID     128
#define NLAY    4
#define NCLS    16
#define NCANDE  100000
#define EMBW    512           // NLAY*HID
#define BN_EPSF 1e-5f

// ------------------------- persistent device scratch -------------------------
__device__ float g_emb[(size_t)N_NODES * EMBW];
__device__ float g_agg[(size_t)N_NODES * HID];
__device__ float g_z2 [(size_t)N_NODES * HID];
__device__ float g_P  [(size_t)NCANDE * 512];
__device__ float g_stats[2 * HID];
__device__ float g_gemb[N_GRAPH * EMBW];
__device__ float g_cnt [N_GRAPH];
__device__ float g_t1[N_GRAPH * 256];
__device__ float g_t2[N_GRAPH * 128];
__device__ float g_t3[N_GRAPH * 128];
__device__ float g_logits[N_GRAPH * NCLS];
// pre-rounded (tf32-representable) weights
__device__ float g_wc1[NLAY * HID * HID];
__device__ float g_wc2[NLAY * HID * HID];
__device__ float g_w1t[512 * 512];      // combined epW1, transposed [N=512][K=512]
__device__ float g_w2 [256 * 128];
// CSR scratch
__device__ int g_deg[N_NODES];
__device__ int g_off[N_NODES + 1];
__device__ int g_pos[N_NODES];
__device__ int g_csr[N_EDGES];
__device__ int g_bsum[128];

// ------------------------------- small utils --------------------------------
__global__ void zero_kernel(float* p, int n) {
    int i = blockIdx.x * blockDim.x + threadIdx.x;
    if (i < n) p[i] = 0.f;
}
__global__ void zeroi_kernel(int* p, int n) {
    int i = blockIdx.x * blockDim.x + threadIdx.x;
    if (i < n) p[i] = 0;
}

// ----------------------------- tf32 helpers ----------------------------------
__device__ __forceinline__ unsigned f2tf32(float f) {
    unsigned r;
    asm("cvt.rna.tf32.f32 %0, %1;" : "=r"(r) : "f"(f));
    return r;
}
__device__ __forceinline__ float rtf(float f) { return __uint_as_float(f2tf32(f)); }
__device__ __forceinline__ uint4 cvt4(float4 v) {
    uint4 w;
    w.x = f2tf32(v.x); w.y = f2tf32(v.y); w.z = f2tf32(v.z); w.w = f2tf32(v.w);
    return w;
}
__device__ __forceinline__ void mma8(float* d, unsigned a0, unsigned a1, unsigned a2,
                                     unsigned a3, unsigned b0, unsigned b1) {
    asm volatile(
        "mma.sync.aligned.m16n8k8.row.col.f32.tf32.tf32.f32 "
        "{%0,%1,%2,%3}, {%4,%5,%6,%7}, {%8,%9}, {%0,%1,%2,%3};"
        : "+f"(d[0]), "+f"(d[1]), "+f"(d[2]), "+f"(d[3])
        : "r"(a0), "r"(a1), "r"(a2), "r"(a3), "r"(b0), "r"(b1));
}
__device__ __forceinline__ void cp16(unsigned sdst, const void* gsrc, int srcbytes) {
    asm volatile("cp.async.ca.shared.global [%0], [%1], 16, %2;"
                 :: "r"(sdst), "l"(gsrc), "r"(srcbytes));
}
#define CP_COMMIT() asm volatile("cp.async.commit_group;")
#define CP_WAIT0()  asm volatile("cp.async.wait_group 0;" ::: "memory")

// ldmatrix: reg i = matrix i; lane l gets word (row l>>2, chunk l&3) of each.
__device__ __forceinline__ void ldsm4(unsigned& r0, unsigned& r1, unsigned& r2,
                                      unsigned& r3, uint32_t addr) {
    asm volatile("ldmatrix.sync.aligned.m8n8.x4.shared.b16 {%0,%1,%2,%3}, [%4];"
                 : "=r"(r0), "=r"(r1), "=r"(r2), "=r"(r3) : "r"(addr));
}

// round weights once (makes HW tf32 truncation exact == cvt.rna semantics)
__global__ void round_weights_kernel(const float* __restrict__ cW1,
                                     const float* __restrict__ cW2,
                                     const float* __restrict__ epW2,
                                     float* __restrict__ wc1, float* __restrict__ wc2,
                                     float* __restrict__ w2) {
    int i = blockIdx.x * blockDim.x + threadIdx.x;
    if (i < NLAY * HID * HID) { wc1[i] = rtf(cW1[i]); wc2[i] = rtf(cW2[i]); }
    if (i < 256 * 128)  w2[i] = rtf(epW2[i]);
}

// build combined transposed [N=512][K=512] epW1 (halves side by side in N)
__global__ void build_w1t_kernel(const float* __restrict__ epW1, float* __restrict__ w1t) {
    int i = blockIdx.x * blockDim.x + threadIdx.x;   // i = n*512 + k
    if (i >= 512 * 512) return;
    int n = i >> 9, k = i & 511;
    float v = (n < 256) ? epW1[(size_t)k * 256 + n]
                        : epW1[(size_t)(512 + k) * 256 + (n - 256)];
    w1t[i] = rtf(v);
}

// ------------------------------ CSR build ------------------------------------
__global__ void hist_kernel(const int* __restrict__ ei, int* __restrict__ deg) {
    int e = blockIdx.x * blockDim.x + threadIdx.x;
    if (e < N_EDGES) atomicAdd(&deg[ei[N_EDGES + e]], 1);
}

#define SCAN_B 1024
__global__ void scan_block_kernel(const int* __restrict__ deg, int* __restrict__ off,
                                  int* __restrict__ bsum, int n) {
    __shared__ int sh[SCAN_B];
    int g = blockIdx.x * SCAN_B + threadIdx.x;
    int v = (g < n) ? deg[g] : 0;
    sh[threadIdx.x] = v;
    __syncthreads();
#pragma unroll
    for (int o = 1; o < SCAN_B; o <<= 1) {
        int t = (threadIdx.x >= o) ? sh[threadIdx.x - o] : 0;
        __syncthreads();
        sh[threadIdx.x] += t;
        __syncthreads();
    }
    if (g < n) off[g] = sh[threadIdx.x] - v;
    if (threadIdx.x == SCAN_B - 1) bsum[blockIdx.x] = sh[SCAN_B - 1];
}

__global__ void scan_bsum_kernel(int* __restrict__ bsum, int nb) {
    __shared__ int sh[128];
    int v = (threadIdx.x < nb) ? bsum[threadIdx.x] : 0;
    sh[threadIdx.x] = v;
    __syncthreads();
#pragma unroll
    for (int o = 1; o < 128; o <<= 1) {
        int t = (threadIdx.x >= o) ? sh[threadIdx.x - o] : 0;
        __syncthreads();
        sh[threadIdx.x] += t;
        __syncthreads();
    }
    if (threadIdx.x < nb) bsum[threadIdx.x] = sh[threadIdx.x] - v;
}

__global__ void scan_add_kernel(int* __restrict__ off, const int* __restrict__ bsum,
                                int* __restrict__ pos, int n) {
    int g = blockIdx.x * blockDim.x + threadIdx.x;
    if (g < n) {
        int o = off[g] + bsum[g / SCAN_B];
        off[g] = o;
        pos[g] = o;
    }
    if (g == n) off[n] = N_EDGES;
}

__global__ void csr_fill_kernel(const int* __restrict__ ei, int* __restrict__ pos,
                                int* __restrict__ csr) {
    int e = blockIdx.x * blockDim.x + threadIdx.x;
    if (e >= N_EDGES) return;
    int dst = ei[N_EDGES + e];
    int p = atomicAdd(&pos[dst], 1);
    csr[p] = ei[e];
}

// ---------- GIN aggregation: warp-per-node gather (+ fused BN of prev layer) ---
// layer 0: stats==null, reads h=x directly.
// layer l>0: reads z2 of layer l-1, applies BN inline (values == rtf(BN(z2))),
//            and writes the emb slice for layer l-1 (self rows cover all nodes).
__global__ void gin_gather_kernel(const int* __restrict__ off,
                                  const int* __restrict__ csr,
                                  const float* __restrict__ h,
                                  const float* __restrict__ ceps, int layer,
                                  const float* __restrict__ stats,
                                  const float* __restrict__ gamma,
                                  const float* __restrict__ beta,
                                  float* __restrict__ emb_out,
                                  float* __restrict__ agg) {
    int node = (blockIdx.x * blockDim.x + threadIdx.x) >> 5;
    int lane = threadIdx.x & 31;
    if (node >= N_NODES) return;
    int s = off[node], e = off[node + 1];
    float c = 1.f + __ldg(&ceps[layer]);
    float4 acc;

    if (stats) {
        int col = lane * 4;
        float inv_n = 1.f / (float)N_NODES;
        float4 sv = *(const float4*)(stats + col);
        float4 qv = *(const float4*)(stats + HID + col);
        float4 g4 = *(const float4*)(gamma + col);
        float4 b4 = *(const float4*)(beta + col);
        float mx = sv.x * inv_n, my = sv.y * inv_n, mz = sv.z * inv_n, mw = sv.w * inv_n;
        float4 sc, sh;
        sc.x = rsqrtf(qv.x * inv_n - mx * mx + BN_EPSF) * g4.x;
        sc.y = rsqrtf(qv.y * inv_n - my * my + BN_EPSF) * g4.y;
        sc.z = rsqrtf(qv.z * inv_n - mz * mz + BN_EPSF) * g4.z;
        sc.w = rsqrtf(qv.w * inv_n - mw * mw + BN_EPSF) * g4.w;
        sh.x = b4.x - mx * sc.x;
        sh.y = b4.y - my * sc.y;
        sh.z = b4.z - mz * sc.z;
        sh.w = b4.w - mw * sc.w;

        float4 z = __ldg((const float4*)(h + (size_t)node * HID) + lane);
        float4 v;
        v.x = rtf(fmaf(z.x, sc.x, sh.x));
        v.y = rtf(fmaf(z.y, sc.y, sh.y));
        v.z = rtf(fmaf(z.z, sc.z, sh.z));
        v.w = rtf(fmaf(z.w, sc.w, sh.w));
        *((float4*)(emb_out + (size_t)node * EMBW) + lane) = v;   // emb slice l-1
        acc = make_float4(c * v.x, c * v.y, c * v.z, c * v.w);
        for (int i = s; i < e; i++) {
            int src = __ldg(&csr[i]);
            z = __ldg((const float4*)(h + (size_t)src * HID) + lane);
            acc.x += rtf(fmaf(z.x, sc.x, sh.x));
            acc.y += rtf(fmaf(z.y, sc.y, sh.y));
            acc.z += rtf(fmaf(z.z, sc.z, sh.z));
            acc.w += rtf(fmaf(z.w, sc.w, sh.w));
        }
    } else {
        acc = __ldg((const float4*)(h + (size_t)node * HID) + lane);
        acc.x *= c; acc.y *= c; acc.z *= c; acc.w *= c;
        for (int i = s; i < e; i++) {
            int src = __ldg(&csr[i]);
            float4 v = __ldg((const float4*)(h + (size_t)src * HID) + lane);
            acc.x += v.x; acc.y += v.y; acc.z += v.z; acc.w += v.w;
        }
    }
    acc.x = rtf(acc.x); acc.y = rtf(acc.y); acc.z = rtf(acc.z); acc.w = rtf(acc.w);
    *((float4*)(agg + (size_t)node * HID) + lane) = acc;
}

#define SA  36
#define SZ  132
#define SW  136
#define SB  136
#define SBT 36
#define GIN_SMEM ((128 * SZ + 32 * SW) * 4)                 // 84992 B -> 2 CTA/SM
#define WIDE_SMEM ((2 * 128 * SA + 2 * 256 * SBT) * 4)      // 110592 B

// ---- GEMM phase: A persistent in smem (128xSZ), weight chunks reg-prefetched --
__device__ __forceinline__ void gemm128(const unsigned* __restrict__ z1s,
                                        unsigned* __restrict__ Ws,
                                        const float* __restrict__ W,
                                        float acc[4][4][4],
                                        int tid, int warpM, int warpN,
                                        int gid, int tig) {
#pragma unroll
    for (int a = 0; a < 4; a++)
#pragma unroll
        for (int b = 0; b < 4; b++)
#pragma unroll
            for (int c = 0; c < 4; c++) acc[a][b][c] = 0.f;

    int wr = tid >> 5, wcq = (tid & 31) << 2;
    float4 pre[4];
#pragma unroll
    for (int i = 0; i < 4; i++)
        pre[i] = __ldg((const float4*)(W + (size_t)(wr + i * 8) * HID + wcq));

    for (int k0 = 0; k0 < 128; k0 += 32) {
#pragma unroll
        for (int i = 0; i < 4; i++)
            *(uint4*)(Ws + (wr + i * 8) * SW + wcq) = cvt4(pre[i]);
        __syncthreads();
        if (k0 < 96) {
#pragma unroll
            for (int i = 0; i < 4; i++)
                pre[i] = __ldg((const float4*)(W + (size_t)(k0 + 32 + wr + i * 8) * HID + wcq));
        }
#pragma unroll
        for (int ks = 0; ks < 32; ks += 8) {
            unsigned af[4][4], bf[4][2];
#pragma unroll
            for (int mt = 0; mt < 4; mt++) {
                const unsigned* p = z1s + (warpM + mt * 16 + gid) * SZ + k0 + ks + tig;
                af[mt][0] = p[0];
                af[mt][1] = p[8 * SZ];
                af[mt][2] = p[4];
                af[mt][3] = p[8 * SZ + 4];
            }
#pragma unroll
            for (int nt = 0; nt < 4; nt++) {
                const unsigned* p = Ws + (ks + tig) * SW + warpN + nt * 8 + gid;
                bf[nt][0] = p[0];
                bf[nt][1] = p[4 * SW];
            }
#pragma unroll
            for (int mt = 0; mt < 4; mt++)
#pragma unroll
                for (int nt = 0; nt < 4; nt++)
                    mma8(acc[mt][nt], af[mt][0], af[mt][1], af[mt][2], af[mt][3],
                         bf[nt][0], bf[nt][1]);
        }
        __syncthreads();
    }
}

// ---- fused node-layer MLP: z2 = relu(relu(agg@W1+b1)@W2+b2), + BN stats ----
__global__ __launch_bounds__(256, 2)
void gin_mlp_kernel(const float* __restrict__ agg,
                    const float* __restrict__ W1, const float* __restrict__ b1,
                    const float* __restrict__ W2, const float* __restrict__ b2,
                    float* __restrict__ z2out, float* __restrict__ stats) {
    extern __shared__ unsigned dsm[];
    unsigned* z1s = dsm;
    unsigned* Ws  = dsm + 128 * SZ;
    int tid = threadIdx.x;
    int warp = tid >> 5, lane = tid & 31;
    int gid = lane >> 2, tig = lane & 3;
    int row0 = blockIdx.x * 128;
    int warpM = (warp >> 2) * 64;
    int warpN = (warp & 3) * 32;

    {
        unsigned sZ = (unsigned)__cvta_generic_to_shared(z1s);
        int r = tid >> 1, cb = (tid & 1) * 64;
        int gr = row0 + r;
        int ok = (gr < N_NODES) ? 16 : 0;
        const float* src = agg + (size_t)(ok ? gr : 0) * HID + cb;
#pragma unroll
        for (int c = 0; c < 16; c++)
            cp16(sZ + (unsigned)(r * SZ + cb + c * 4) * 4u, src + c * 4, ok);
        CP_COMMIT();
        CP_WAIT0();
    }
    __syncthreads();

    float acc[4][4][4];

    gemm128(z1s, Ws, W1, acc, tid, warpM, warpN, gid, tig);
#pragma unroll
    for (int mt = 0; mt < 4; mt++)
#pragma unroll
        for (int half = 0; half < 2; half++) {
            int r = warpM + mt * 16 + gid + half * 8;
#pragma unroll
            for (int nt = 0; nt < 4; nt++) {
                int gc = warpN + nt * 8 + tig * 2;
                float vx = fmaxf(acc[mt][nt][half * 2 + 0] + __ldg(&b1[gc]), 0.f);
                float vy = fmaxf(acc[mt][nt][half * 2 + 1] + __ldg(&b1[gc + 1]), 0.f);
                z1s[r * SZ + gc]     = f2tf32(vx);
                z1s[r * SZ + gc + 1] = f2tf32(vy);
            }
        }
    __syncthreads();

    gemm128(z1s, Ws, W2, acc, tid, warpM, warpN, gid, tig);

    float* sS = (float*)Ws;
    float* sQ = sS + 128;
    if (tid < 256) ((float*)Ws)[tid] = 0.f;
    __syncthreads();

    float sumS[4][2] = {}, sumQ[4][2] = {};
#pragma unroll
    for (int mt = 0; mt < 4; mt++)
#pragma unroll
        for (int half = 0; half < 2; half++) {
            int gr = row0 + warpM + mt * 16 + gid + half * 8;
            if (gr >= N_NODES) continue;
#pragma unroll
            for (int nt = 0; nt < 4; nt++) {
                int gc = warpN + nt * 8 + tig * 2;
                float vx = fmaxf(acc[mt][nt][half * 2 + 0] + __ldg(&b2[gc]), 0.f);
                float vy = fmaxf(acc[mt][nt][half * 2 + 1] + __ldg(&b2[gc + 1]), 0.f);
                *(float2*)(z2out + (size_t)gr * HID + gc) = make_float2(vx, vy);
                sumS[nt][0] += vx; sumQ[nt][0] += vx * vx;
                sumS[nt][1] += vy; sumQ[nt][1] += vy * vy;
            }
        }
#pragma unroll
    for (int nt = 0; nt < 4; nt++) {
        int gc = warpN + nt * 8 + tig * 2;
        atomicAdd(&sS[gc],     sumS[nt][0]);
        atomicAdd(&sS[gc + 1], sumS[nt][1]);
        atomicAdd(&sQ[gc],     sumQ[nt][0]);
        atomicAdd(&sQ[gc + 1], sumQ[nt][1]);
    }
    __syncthreads();
    if (tid < 128) {
        atomicAdd(&stats[tid],       sS[tid]);
        atomicAdd(&stats[HID + tid], sQ[tid]);
    }
}

// ------- WIDE P-GEMM with ldmatrix (coalesced staging): 128x256, K=512 -------
__global__ __launch_bounds__(256, 1)
void tf32_gemm_wide(const float* __restrict__ A, int lda,
                    const float* __restrict__ Bt,
                    float* __restrict__ C, int ldc, int M) {
    extern __shared__ float sm[];
    float* Ab[2] = { sm, sm + 128 * SA };
    float* Bb[2] = { sm + 2 * 128 * SA, sm + 2 * 128 * SA + 256 * SBT };
    int tid = threadIdx.x;
    int warp = tid >> 5, lane = tid & 31;
    int row0 = blockIdx.y * 128;
    int col0 = blockIdx.x * 256;
    int warpM = (warp >> 2) * 64;
    int warpN = (warp & 3) * 64;

    int ar = tid >> 3, acq = (tid & 7) << 2;

    int a_row = lane & 15, a_koff = (lane >> 4) * 4;
    int b_row = lane & 7, b_koff = ((lane >> 3) & 1) * 4;
    int b_nsel = (lane >> 4);

    float acc[4][8][4];
#pragma unroll
    for (int a = 0; a < 4; a++)
#pragma unroll
        for (int b = 0; b < 8; b++)
#pragma unroll
            for (int c = 0; c < 4; c++) acc[a][b][c] = 0.f;

    {
        unsigned sA = (unsigned)__cvta_generic_to_shared(Ab[0]);
        unsigned sB = (unsigned)__cvta_generic_to_shared(Bb[0]);
#pragma unroll
        for (int i = 0; i < 4; i++) {
            int r = ar + i * 32;
            int gr = row0 + r;
            int ok = (gr < M) ? 16 : 0;
            cp16(sA + (unsigned)(r * SA + acq) * 4u,
                 A + (size_t)(ok ? gr : 0) * lda + acq, ok);
        }
#pragma unroll
        for (int i = 0; i < 8; i++) {
            int f = tid + i * 256;
            int r = f >> 3, c = (f & 7) << 2;
            cp16(sB + (unsigned)(r * SBT + c) * 4u,
                 Bt + (size_t)(col0 + r) * 512 + c, 16);
        }
        CP_COMMIT();
    }

    for (int t = 0; t < 16; t++) {
        CP_WAIT0();
        __syncthreads();
        if (t + 1 < 16) {
            int nb = (t + 1) & 1;
            int k0 = (t + 1) << 5;
            unsigned sA = (unsigned)__cvta_generic_to_shared(Ab[nb]);
            unsigned sB = (unsigned)__cvta_generic_to_shared(Bb[nb]);
#pragma unroll
            for (int i = 0; i < 4; i++) {
                int r = ar + i * 32;
                int gr = row0 + r;
                int ok = (gr < M) ? 16 : 0;
                cp16(sA + (unsigned)(r * SA + acq) * 4u,
                     A + (size_t)(ok ? gr : 0) * lda + k0 + acq, ok);
            }
#pragma unroll
            for (int i = 0; i < 8; i++) {
                int f = tid + i * 256;
                int r = f >> 3, c = (f & 7) << 2;
                cp16(sB + (unsigned)(r * SBT + c) * 4u,
                     Bt + (size_t)(col0 + r) * 512 + k0 + c, 16);
            }
            CP_COMMIT();
        }
        unsigned aBase = (unsigned)__cvta_generic_to_shared(Ab[t & 1]);
        unsigned bBase = (unsigned)__cvta_generic_to_shared(Bb[t & 1]);
#pragma unroll
        for (int ks = 0; ks < 32; ks += 8) {
            unsigned af[4][4], bf[8][2];
#pragma unroll
            for (int mt = 0; mt < 4; mt++) {
                uint32_t addr = aBase +
                    (unsigned)((warpM + mt * 16 + a_row) * SA + ks + a_koff) * 4u;
                ldsm4(af[mt][0], af[mt][1], af[mt][2], af[mt][3], addr);
            }
#pragma unroll
            for (int j = 0; j < 4; j++) {
                uint32_t addr = bBase +
                    (unsigned)((warpN + (2 * j + b_nsel) * 8 + b_row) * SBT
                               + ks + b_koff) * 4u;
                ldsm4(bf[2 * j][0], bf[2 * j][1], bf[2 * j + 1][0], bf[2 * j + 1][1],
                      addr);
            }
#pragma unroll
            for (int mt = 0; mt < 4; mt++)
#pragma unroll
                for (int nt = 0; nt < 8; nt++)
                    mma8(acc[mt][nt], af[mt][0], af[mt][1], af[mt][2], af[mt][3],
                         bf[nt][0], bf[nt][1]);
        }
    }

    int gid = lane >> 2, tig = lane & 3;
#pragma unroll
    for (int mt = 0; mt < 4; mt++) {
#pragma unroll
        for (int half = 0; half < 2; half++) {
            int gr = row0 + warpM + mt * 16 + gid + half * 8;
            if (gr >= M) continue;
#pragma unroll
            for (int nt = 0; nt < 8; nt++) {
                int gc = col0 + warpN + nt * 8 + tig * 2;
                float2 v;
                v.x = acc[mt][nt][half * 2 + 0];
                v.y = acc[mt][nt][half * 2 + 1];
                *(float2*)(C + (size_t)gr * ldc + gc) = v;
            }
        }
    }
}

// ------------- fused edge kernel: gather + GEMM(K=256) + score dot -----------
__global__ __launch_bounds__(256, 2)
void ep_fused_kernel(const int* __restrict__ ce,
                     const float* __restrict__ P,
                     const float* __restrict__ b1,
                     const float* __restrict__ W2,
                     const float* __restrict__ b2,
                     const float* __restrict__ w3,
                     float* __restrict__ score) {
    __shared__ unsigned As[128 * SA];
    __shared__ unsigned Bs[32 * SB];
    int tid = threadIdx.x;
    int warp = tid >> 5, lane = tid & 31;
    int gid = lane >> 2, tig = lane & 3;
    int row0 = blockIdx.x * 128;
    int warpM = (warp >> 2) * 64;
    int warpN = (warp & 3) * 32;

    int rloc[4], c0v[4], c1v[4], cqv[4];
#pragma unroll
    for (int i = 0; i < 4; i++) {
        int f = tid + i * 256;
        rloc[i] = f >> 3;
        cqv[i] = (f & 7) << 2;
        int gr = row0 + rloc[i];
        if (gr < NCANDE) {
            c0v[i] = __ldg(&ce[gr]);
            c1v[i] = __ldg(&ce[NCANDE + gr]);
        } else { c0v[i] = 0; c1v[i] = 0; }
    }

    float acc[4][4][4];
#pragma unroll
    for (int a = 0; a < 4; a++)
#pragma unroll
        for (int b = 0; b < 4; b++)
#pragma unroll
            for (int c = 0; c < 4; c++) acc[a][b][c] = 0.f;

    for (int k0 = 0; k0 < 256; k0 += 32) {
#pragma unroll
        for (int i = 0; i < 4; i++) {
            int r = rloc[i], cq = cqv[i];
            float4 v = make_float4(0.f, 0.f, 0.f, 0.f);
            if (row0 + r < NCANDE) {
                float4 a = __ldg((const float4*)(P + (size_t)c0v[i] * 512 + k0 + cq));
                float4 b = __ldg((const float4*)(P + (size_t)c1v[i] * 512 + 256 + k0 + cq));
                float4 bb = __ldg((const float4*)(b1 + k0 + cq));
                v.x = fmaxf(a.x + b.x + bb.x, 0.f);
                v.y = fmaxf(a.y + b.y + bb.y, 0.f);
                v.z = fmaxf(a.z + b.z + bb.z, 0.f);
                v.w = fmaxf(a.w + b.w + bb.w, 0.f);
            }
            *(uint4*)(As + r * SA + cq) = cvt4(v);
        }
#pragma unroll
        for (int i = 0; i < 4; i++) {
            int f = tid + i * 256;
            int r = f >> 5, cq = (f & 31) << 2;
            float4 v = __ldg((const float4*)(W2 + (size_t)(k0 + r) * HID + cq));
            *(uint4*)(Bs + r * SB + cq) =
                make_uint4(__float_as_uint(v.x), __float_as_uint(v.y),
                           __float_as_uint(v.z), __float_as_uint(v.w));
        }
        __syncthreads();
#pragma unroll
        for (int ks = 0; ks < 32; ks += 8) {
            unsigned af[4][4], bf[4][2];
#pragma unroll
            for (int mt = 0; mt < 4; mt++) {
                const unsigned* p = As + (warpM + mt * 16 + gid) * SA + ks + tig;
                af[mt][0] = p[0];
                af[mt][1] = p[8 * SA];
                af[mt][2] = p[4];
                af[mt][3] = p[8 * SA + 4];
            }
#pragma unroll
            for (int nt = 0; nt < 4; nt++) {
                const unsigned* p = Bs + (ks + tig) * SB + warpN + nt * 8 + gid;
                bf[nt][0] = p[0];
                bf[nt][1] = p[4 * SB];
            }
#pragma unroll
            for (int mt = 0; mt < 4; mt++)
#pragma unroll
                for (int nt = 0; nt < 4; nt++)
                    mma8(acc[mt][nt], af[mt][0], af[mt][1], af[mt][2], af[mt][3],
                         bf[nt][0], bf[nt][1]);
        }
        __syncthreads();
    }

#pragma unroll
    for (int mt = 0; mt < 4; mt++)
#pragma unroll
        for (int half = 0; half < 2; half++) {
            int gr = row0 + warpM + mt * 16 + gid + half * 8;
            float p = 0.f;
#pragma unroll
            for (int nt = 0; nt < 4; nt++) {
                int gc = warpN + nt * 8 + tig * 2;
                float vx = fmaxf(acc[mt][nt][half * 2 + 0] + __ldg(&b2[gc]), 0.f);
                float vy = fmaxf(acc[mt][nt][half * 2 + 1] + __ldg(&b2[gc + 1]), 0.f);
                p = fmaf(vx, __ldg(&w3[gc]), p);
                p = fmaf(vy, __ldg(&w3[gc + 1]), p);
            }
            p += __shfl_xor_sync(0xffffffffu, p, 1);
            p += __shfl_xor_sync(0xffffffffu, p, 2);
            if (tig == 0 && gr < NCANDE) atomicAdd(&score[gr], p);
        }
}

__global__ void sigmoid_kernel(float* __restrict__ s, const float* __restrict__ b, int n) {
    int i = blockIdx.x * blockDim.x + threadIdx.x;
    if (i < n) s[i] = 1.f / (1.f + expf(-(s[i] + b[0])));
}

// ------------------------------ batch norm apply (last layer only) ------------
__global__ void bn_apply_kernel(const float* __restrict__ Z,
                                const float* __restrict__ stats,
                                const float* __restrict__ gamma,
                                const float* __restrict__ beta,
                                float* __restrict__ out, int ostride) {
    int idx = blockIdx.x * blockDim.x + threadIdx.x;
    if (idx >= N_NODES * HID) return;
    int row = idx / HID, col = idx - row * HID;
    float inv_n = 1.f / (float)N_NODES;
    float mu = stats[col] * inv_n;
    float var = stats[HID + col] * inv_n - mu * mu;
    float scale = rsqrtf(var + BN_EPSF) * gamma[col];
    float shift = beta[col] - mu * scale;
    out[(size_t)row * ostride + col] = rtf(fmaf(Z[idx], scale, shift));
}

// ------------------------------- pooling -------------------------------------
#define POOL_ROWS 1024
__global__ void pool_sum_kernel(const float* __restrict__ emb,
                                const int* __restrict__ batch,
                                float* __restrict__ gsum) {
    int col = blockIdx.y * 128 + threadIdx.x;
    int r0 = blockIdx.x * POOL_ROWS;
    int r1 = min(r0 + POOL_ROWS, N_NODES);
    float acc = 0.f;
    int cur = batch[r0];
    for (int r = r0; r < r1; r++) {
        int b = batch[r];
        if (b != cur) {
            atomicAdd(&gsum[(size_t)cur * EMBW + col], acc);
            acc = 0.f; cur = b;
        }
        acc += emb[(size_t)r * EMBW + col];
    }
    atomicAdd(&gsum[(size_t)cur * EMBW + col], acc);
}

__global__ void count_kernel(const int* __restrict__ batch, float* __restrict__ cnt) {
    __shared__ int hist[N_GRAPH];
    int tid = threadIdx.x;
    if (tid < N_GRAPH) hist[tid] = 0;
    __syncthreads();
    for (int i = blockIdx.x * blockDim.x + tid; i < N_NODES; i += gridDim.x * blockDim.x)
        atomicAdd(&hist[batch[i]], 1);
    __syncthreads();
    if (tid < N_GRAPH && hist[tid]) atomicAdd(&cnt[tid], (float)hist[tid]);
}

__global__ void pool_div_kernel(float* __restrict__ gsum, const float* __restrict__ cnt) {
    int i = blockIdx.x * blockDim.x + threadIdx.x;
    if (i >= N_GRAPH * EMBW) return;
    int g = i / EMBW;
    gsum[i] = gsum[i] / fmaxf(cnt[g], 1.f);
}

// ------------------------- small MLP (classifier) -----------------------------
__global__ void small_mlp_kernel(const float* __restrict__ A,
                                 const float* __restrict__ B,
                                 const float* __restrict__ bias,
                                 float* __restrict__ C,
                                 int M, int N, int K, int relu) {
    int idx = blockIdx.x * blockDim.x + threadIdx.x;
    if (idx >= M * N) return;
    int i = idx / N, j = idx - i * N;
    float s = bias[j];
    const float* a = A + (size_t)i * K;
    for (int k = 0; k < K; k++) s = fmaf(a[k], B[(size_t)k * N + j], s);
    if (relu) s = fmaxf(s, 0.f);
    C[idx] = s;
}

__global__ void logsoftmax_kernel(const float* __restrict__ in, float* __restrict__ out) {
    int g = blockIdx.x;
    int lane = threadIdx.x;
    float v = (lane < NCLS) ? in[g * NCLS + lane] : -INFINITY;
    float m = v;
#pragma unroll
    for (int o = 16; o > 0; o >>= 1) m = fmaxf(m, __shfl_xor_sync(0xffffffffu, m, o));
    float e = (lane < NCLS) ? expf(v - m) : 0.f;
    float s = e;
#pragma unroll
    for (int o = 16; o > 0; o >>= 1) s += __shfl_xor_sync(0xffffffffu, s, o);
    if (lane < NCLS) out[g * NCLS + lane] = v - m - logf(s);
}

// --------------------------------- host --------------------------------------
static void* sym_addr(const void* sym) {
    void* p = nullptr;
    cudaGetSymbolAddress(&p, sym);
    return p;
}

extern "C" void kernel_launch(void* const* d_in, const int* in_sizes, int n_in,
                              void* d_out, int out_size) {
    (void)n_in; (void)out_size;
    const float *x, *cW1, *cb1, *cW2, *cb2, *cgamma, *cbeta, *ceps;
    const float *ncW1, *ncb1, *ncW2, *ncb2, *ncW3, *ncb3, *ncW4, *ncb4;
    const float *epW1, *epb1, *epW2, *epb2, *epW3, *epb3;
    const int *edge_index, *batch, *cand;
    bool dict_order = (in_sizes[1] == 2 * N_EDGES);
    if (dict_order) {
        x          = (const float*)d_in[0];
        edge_index = (const int*)  d_in[1];
        batch      = (const int*)  d_in[2];
        cand       = (const int*)  d_in[3];
        cW1 = (const float*)d_in[4];  cb1 = (const float*)d_in[5];
        cW2 = (const float*)d_in[6];  cb2 = (const float*)d_in[7];
        cgamma = (const float*)d_in[8]; cbeta = (const float*)d_in[9];
        ceps = (const float*)d_in[10];
        ncW1 = (const float*)d_in[11]; ncb1 = (const float*)d_in[12];
        ncW2 = (const float*)d_in[13]; ncb2 = (const float*)d_in[14];
        ncW3 = (const float*)d_in[15]; ncb3 = (const float*)d_in[16];
        ncW4 = (const float*)d_in[17]; ncb4 = (const float*)d_in[18];
        epW1 = (const float*)d_in[19]; epb1 = (const float*)d_in[20];
        epW2 = (const float*)d_in[21]; epb2 = (const float*)d_in[22];
        epW3 = (const float*)d_in[23]; epb3 = (const float*)d_in[24];
    } else {
        x = (const float*)d_in[0];
        cW1 = (const float*)d_in[1];  cb1 = (const float*)d_in[2];
        cW2 = (const float*)d_in[3];  cb2 = (const float*)d_in[4];
        cgamma = (const float*)d_in[5]; cbeta = (const float*)d_in[6];
        ceps = (const float*)d_in[7];
        ncW1 = (const float*)d_in[8];  ncb1 = (const float*)d_in[9];
        ncW2 = (const float*)d_in[10]; ncb2 = (const float*)d_in[11];
        ncW3 = (const float*)d_in[12]; ncb3 = (const float*)d_in[13];
        ncW4 = (const float*)d_in[14]; ncb4 = (const float*)d_in[15];
        epW1 = (const float*)d_in[16]; epb1 = (const float*)d_in[17];
        epW2 = (const float*)d_in[18]; epb2 = (const float*)d_in[19];
        epW3 = (const float*)d_in[20]; epb3 = (const float*)d_in[21];
        edge_index = (const int*)d_in[22];
        batch      = (const int*)d_in[23];
        cand       = (const int*)d_in[24];
    }
    float* out = (float*)d_out;

    float* p_emb  = (float*)sym_addr(g_emb);
    float* p_agg  = (float*)sym_addr(g_agg);
    float* p_z2   = (float*)sym_addr(g_z2);
    float* p_P    = (float*)sym_addr(g_P);
    float* p_st   = (float*)sym_addr(g_stats);
    float* p_gemb = (float*)sym_addr(g_gemb);
    float* p_cnt  = (float*)sym_addr(g_cnt);
    float* p_t1   = (float*)sym_addr(g_t1);
    float* p_t2   = (float*)sym_addr(g_t2);
    float* p_t3   = (float*)sym_addr(g_t3);
    float* p_lg   = (float*)sym_addr(g_logits);
    float* p_wc1  = (float*)sym_addr(g_wc1);
    float* p_wc2  = (float*)sym_addr(g_wc2);
    float* p_w1t  = (float*)sym_addr(g_w1t);
    float* p_w2   = (float*)sym_addr(g_w2);
    int* p_deg  = (int*)sym_addr(g_deg);
    int* p_off  = (int*)sym_addr(g_off);
    int* p_pos  = (int*)sym_addr(g_pos);
    int* p_csr  = (int*)sym_addr(g_csr);
    int* p_bsum = (int*)sym_addr(g_bsum);

    static bool attr_done = false;
    if (!attr_done) {
        cudaFuncSetAttribute(gin_mlp_kernel,
                             cudaFuncAttributeMaxDynamicSharedMemorySize, GIN_SMEM);
        cudaFuncSetAttribute(tf32_gemm_wide,
                             cudaFuncAttributeMaxDynamicSharedMemorySize, WIDE_SMEM);
        attr_done = true;
    }

    const int T = 256;
    const int NODE_BLKS = (N_NODES + 127) / 128;
    const int CAND_BLKS = (NCANDE + 127) / 128;
    const int nScanBlocks = (N_NODES + SCAN_B - 1) / SCAN_B;

    // ============ weight prep ============
    round_weights_kernel<<<(NLAY * HID * HID + T - 1) / T, T>>>(cW1, cW2, epW2,
                                                                p_wc1, p_wc2, p_w2);
    build_w1t_kernel<<<(512 * 512 + T - 1) / T, T>>>(epW1, p_w1t);

    // ================= CSR build =================
    zeroi_kernel<<<(N_NODES + T - 1) / T, T>>>(p_deg, N_NODES);
    hist_kernel<<<(N_EDGES + T - 1) / T, T>>>(edge_index, p_deg);
    scan_block_kernel<<<nScanBlocks, SCAN_B>>>(p_deg, p_off, p_bsum, N_NODES);
    scan_bsum_kernel<<<1, 128>>>(p_bsum, nScanBlocks);
    scan_add_kernel<<<(N_NODES + T) / T, T>>>(p_off, p_bsum, p_pos, N_NODES);
    csr_fill_kernel<<<(N_EDGES + T - 1) / T, T>>>(edge_index, p_pos, p_csr);

    // ================= GIN layers (BN of layer l-1 fused into gather l) =======
    for (int l = 0; l < NLAY; l++) {
        const float* h = (l == 0) ? x : p_z2;
        const float* st = (l == 0) ? nullptr : p_st;
        const float* gm = (l == 0) ? nullptr : (cgamma + (l - 1) * HID);
        const float* bt = (l == 0) ? nullptr : (cbeta + (l - 1) * HID);
        float* eo = (l == 0) ? nullptr : (p_emb + (l - 1) * HID);

        gin_gather_kernel<<<(N_NODES * 32 + T - 1) / T, T>>>(
            p_off, p_csr, h, ceps, l, st, gm, bt, eo, p_agg);
        zero_kernel<<<1, 256>>>(p_st, 2 * HID);
        gin_mlp_kernel<<<NODE_BLKS, 256, GIN_SMEM>>>(
            p_agg,
            p_wc1 + (size_t)l * HID * HID, cb1 + l * HID,
            p_wc2 + (size_t)l * HID * HID, cb2 + l * HID,
            p_z2, p_st);
    }
    // final layer's BN -> emb slice 3
    bn_apply_kernel<<<(N_NODES * HID + T - 1) / T, T>>>(
        p_z2, p_st, cgamma + 3 * HID, cbeta + 3 * HID, p_emb + 3 * HID, EMBW);

    // ================= global mean pool =================
    zero_kernel<<<(N_GRAPH * EMBW + T - 1) / T, T>>>(p_gemb, N_GRAPH * EMBW);
    zero_kernel<<<1, 64>>>(p_cnt, N_GRAPH);
    {
        dim3 pg((N_NODES + POOL_ROWS - 1) / POOL_ROWS, EMBW / 128);
        pool_sum_kernel<<<pg, 128>>>(p_emb, batch, p_gemb);
    }
    count_kernel<<<128, 256>>>(batch, p_cnt);
    pool_div_kernel<<<(N_GRAPH * EMBW + T - 1) / T, T>>>(p_gemb, p_cnt);

    // ================= node classifier =================
    small_mlp_kernel<<<(N_GRAPH * 256 + T - 1) / T, T>>>(p_gemb, ncW1, ncb1, p_t1,
                                                         N_GRAPH, 256, EMBW, 1);
    small_mlp_kernel<<<(N_GRAPH * 128 + T - 1) / T, T>>>(p_t1, ncW2, ncb2, p_t2,
                                                         N_GRAPH, 128, 256, 1);
    small_mlp_kernel<<<(N_GRAPH * 128 + T - 1) / T, T>>>(p_t2, ncW3, ncb3, p_t3,
                                                         N_GRAPH, 128, 128, 1);
    small_mlp_kernel<<<(N_GRAPH * NCLS + T - 1) / T, T>>>(p_t3, ncW4, ncb4, p_lg,
                                                          N_GRAPH, NCLS, 128, 0);
    logsoftmax_kernel<<<N_GRAPH, 32>>>(p_lg, out);

    // ================= edge predictor =================
    {
        dim3 wg(2, NODE_BLKS);    // N=512 in two 256-wide tiles
        tf32_gemm_wide<<<wg, 256, WIDE_SMEM>>>(p_emb, EMBW, p_w1t, p_P, 512, N_NODES);
    }
    float* scores = out + N_GRAPH * NCLS;
    zero_kernel<<<(NCANDE + T - 1) / T, T>>>(scores, NCANDE);
    ep_fused_kernel<<<CAND_BLKS, 256>>>(cand, p_P, epb1, p_w2, epb2, epW3, scores);
    sigmoid_kernel<<<(NCANDE + T - 1) / T, T>>>(scores, epb3, NCANDE);
}

// round 14
// speedup vs baseline: 1.0066x; 1.0066x over previous
#include <cuda_runtime.h>
#include <math.h>
#include <stdint.h>

#define N_NODES 100000
#define N_EDGES 1600000
#define N_GRAPH 64
#define HID     128
#define NLAY    4
#define NCLS    16
#define NCANDE  100000
#define EMBW    512           // NLAY*HID
#define BN_EPSF 1e-5f

// ------------------------- persistent device scratch -------------------------
__device__ float g_emb[(size_t)N_NODES * EMBW];
__device__ float g_agg[(size_t)N_NODES * HID];
__device__ float g_z2 [(size_t)N_NODES * HID];
__device__ float g_P  [(size_t)NCANDE * 512];
__device__ float g_stats[2 * HID];
__device__ float g_gemb[N_GRAPH * EMBW];
__device__ float g_cnt [N_GRAPH];
__device__ float g_t1[N_GRAPH * 256];
__device__ float g_t2[N_GRAPH * 128];
__device__ float g_t3[N_GRAPH * 128];
__device__ float g_logits[N_GRAPH * NCLS];
// pre-rounded (tf32-representable) weights
__device__ float g_wc1[NLAY * HID * HID];
__device__ float g_wc2[NLAY * HID * HID];
__device__ float g_w1t[512 * 512];      // combined epW1, transposed [N=512][K=512]
__device__ float g_w2 [256 * 128];
// CSR scratch
__device__ int g_deg[N_NODES];
__device__ int g_off[N_NODES + 1];
__device__ int g_pos[N_NODES];
__device__ int g_csr[N_EDGES];
__device__ int g_bsum[128];

// ------------------------------- small utils --------------------------------
__global__ void zero_kernel(float* p, int n) {
    int i = blockIdx.x * blockDim.x + threadIdx.x;
    if (i < n) p[i] = 0.f;
}
__global__ void zeroi_kernel(int* p, int n) {
    int i = blockIdx.x * blockDim.x + threadIdx.x;
    if (i < n) p[i] = 0;
}

// ----------------------------- tf32 helpers ----------------------------------
__device__ __forceinline__ unsigned f2tf32(float f) {
    unsigned r;
    asm("cvt.rna.tf32.f32 %0, %1;" : "=r"(r) : "f"(f));
    return r;
}
__device__ __forceinline__ float rtf(float f) { return __uint_as_float(f2tf32(f)); }
__device__ __forceinline__ uint4 cvt4(float4 v) {
    uint4 w;
    w.x = f2tf32(v.x); w.y = f2tf32(v.y); w.z = f2tf32(v.z); w.w = f2tf32(v.w);
    return w;
}
__device__ __forceinline__ void mma8(float* d, unsigned a0, unsigned a1, unsigned a2,
                                     unsigned a3, unsigned b0, unsigned b1) {
    asm volatile(
        "mma.sync.aligned.m16n8k8.row.col.f32.tf32.tf32.f32 "
        "{%0,%1,%2,%3}, {%4,%5,%6,%7}, {%8,%9}, {%0,%1,%2,%3};"
        : "+f"(d[0]), "+f"(d[1]), "+f"(d[2]), "+f"(d[3])
        : "r"(a0), "r"(a1), "r"(a2), "r"(a3), "r"(b0), "r"(b1));
}
__device__ __forceinline__ void cp16(unsigned sdst, const void* gsrc, int srcbytes) {
    asm volatile("cp.async.ca.shared.global [%0], [%1], 16, %2;"
                 :: "r"(sdst), "l"(gsrc), "r"(srcbytes));
}
#define CP_COMMIT() asm volatile("cp.async.commit_group;")
#define CP_WAIT0()  asm volatile("cp.async.wait_group 0;" ::: "memory")

// ldmatrix: reg i = matrix i; lane l gets word (row l>>2, chunk l&3) of each.
__device__ __forceinline__ void ldsm4(unsigned& r0, unsigned& r1, unsigned& r2,
                                      unsigned& r3, uint32_t addr) {
    asm volatile("ldmatrix.sync.aligned.m8n8.x4.shared.b16 {%0,%1,%2,%3}, [%4];"
                 : "=r"(r0), "=r"(r1), "=r"(r2), "=r"(r3) : "r"(addr));
}

// round weights once (makes HW tf32 truncation exact == cvt.rna semantics)
__global__ void round_weights_kernel(const float* __restrict__ cW1,
                                     const float* __restrict__ cW2,
                                     const float* __restrict__ epW2,
                                     float* __restrict__ wc1, float* __restrict__ wc2,
                                     float* __restrict__ w2) {
    int i = blockIdx.x * blockDim.x + threadIdx.x;
    if (i < NLAY * HID * HID) { wc1[i] = rtf(cW1[i]); wc2[i] = rtf(cW2[i]); }
    if (i < 256 * 128)  w2[i] = rtf(epW2[i]);
}

// build combined transposed [N=512][K=512] epW1 (halves side by side in N)
__global__ void build_w1t_kernel(const float* __restrict__ epW1, float* __restrict__ w1t) {
    int i = blockIdx.x * blockDim.x + threadIdx.x;   // i = n*512 + k
    if (i >= 512 * 512) return;
    int n = i >> 9, k = i & 511;
    float v = (n < 256) ? epW1[(size_t)k * 256 + n]
                        : epW1[(size_t)(512 + k) * 256 + (n - 256)];
    w1t[i] = rtf(v);
}

// ------------------------------ CSR build ------------------------------------
__global__ void hist_kernel(const int* __restrict__ ei, int* __restrict__ deg) {
    int e = blockIdx.x * blockDim.x + threadIdx.x;
    if (e < N_EDGES) atomicAdd(&deg[ei[N_EDGES + e]], 1);
}

#define SCAN_B 1024
__global__ void scan_block_kernel(const int* __restrict__ deg, int* __restrict__ off,
                                  int* __restrict__ bsum, int n) {
    __shared__ int sh[SCAN_B];
    int g = blockIdx.x * SCAN_B + threadIdx.x;
    int v = (g < n) ? deg[g] : 0;
    sh[threadIdx.x] = v;
    __syncthreads();
#pragma unroll
    for (int o = 1; o < SCAN_B; o <<= 1) {
        int t = (threadIdx.x >= o) ? sh[threadIdx.x - o] : 0;
        __syncthreads();
        sh[threadIdx.x] += t;
        __syncthreads();
    }
    if (g < n) off[g] = sh[threadIdx.x] - v;
    if (threadIdx.x == SCAN_B - 1) bsum[blockIdx.x] = sh[SCAN_B - 1];
}

__global__ void scan_bsum_kernel(int* __restrict__ bsum, int nb) {
    __shared__ int sh[128];
    int v = (threadIdx.x < nb) ? bsum[threadIdx.x] : 0;
    sh[threadIdx.x] = v;
    __syncthreads();
#pragma unroll
    for (int o = 1; o < 128; o <<= 1) {
        int t = (threadIdx.x >= o) ? sh[threadIdx.x - o] : 0;
        __syncthreads();
        sh[threadIdx.x] += t;
        __syncthreads();
    }
    if (threadIdx.x < nb) bsum[threadIdx.x] = sh[threadIdx.x] - v;
}

__global__ void scan_add_kernel(int* __restrict__ off, const int* __restrict__ bsum,
                                int* __restrict__ pos, int n) {
    int g = blockIdx.x * blockDim.x + threadIdx.x;
    if (g < n) {
        int o = off[g] + bsum[g / SCAN_B];
        off[g] = o;
        pos[g] = o;
    }
    if (g == n) off[n] = N_EDGES;
}

__global__ void csr_fill_kernel(const int* __restrict__ ei, int* __restrict__ pos,
                                int* __restrict__ csr) {
    int e = blockIdx.x * blockDim.x + threadIdx.x;
    if (e >= N_EDGES) return;
    int dst = ei[N_EDGES + e];
    int p = atomicAdd(&pos[dst], 1);
    csr[p] = ei[e];
}

// ------------------- GIN aggregation: warp-per-node gather --------------------
__global__ void gin_gather_kernel(const int* __restrict__ off,
                                  const int* __restrict__ csr,
                                  const float* __restrict__ h, int hstride,
                                  const float* __restrict__ ceps, int layer,
                                  float* __restrict__ agg) {
    int node = (blockIdx.x * blockDim.x + threadIdx.x) >> 5;
    int lane = threadIdx.x & 31;
    if (node >= N_NODES) return;
    int s = off[node], e = off[node + 1];
    float c = 1.f + __ldg(&ceps[layer]);
    float4 acc = __ldg((const float4*)(h + (size_t)node * hstride) + lane);
    acc.x *= c; acc.y *= c; acc.z *= c; acc.w *= c;
    for (int i = s; i < e; i++) {
        int src = __ldg(&csr[i]);
        float4 v = __ldg((const float4*)(h + (size_t)src * hstride) + lane);
        acc.x += v.x; acc.y += v.y; acc.z += v.z; acc.w += v.w;
    }
    acc.x = rtf(acc.x); acc.y = rtf(acc.y); acc.z = rtf(acc.z); acc.w = rtf(acc.w);
    *((float4*)(agg + (size_t)node * HID) + lane) = acc;
}

#define SA  36
#define SZ  132
#define SW  136
#define SB  136
#define SBT 36
#define GIN_SMEM ((128 * SZ + 32 * SW) * 4)                 // 84992 B -> 2 CTA/SM
#define WIDE_SMEM ((2 * 128 * SA + 2 * 256 * SBT) * 4)      // 110592 B

// ---- GEMM phase: A persistent in smem (128xSZ), weight chunks reg-prefetched --
__device__ __forceinline__ void gemm128(const unsigned* __restrict__ z1s,
                                        unsigned* __restrict__ Ws,
                                        const float* __restrict__ W,
                                        float acc[4][4][4],
                                        int tid, int warpM, int warpN,
                                        int gid, int tig) {
#pragma unroll
    for (int a = 0; a < 4; a++)
#pragma unroll
        for (int b = 0; b < 4; b++)
#pragma unroll
            for (int c = 0; c < 4; c++) acc[a][b][c] = 0.f;

    int wr = tid >> 5, wcq = (tid & 31) << 2;
    float4 pre[4];
#pragma unroll
    for (int i = 0; i < 4; i++)
        pre[i] = __ldg((const float4*)(W + (size_t)(wr + i * 8) * HID + wcq));

    for (int k0 = 0; k0 < 128; k0 += 32) {
#pragma unroll
        for (int i = 0; i < 4; i++)
            *(uint4*)(Ws + (wr + i * 8) * SW + wcq) = cvt4(pre[i]);
        __syncthreads();
        if (k0 < 96) {
#pragma unroll
            for (int i = 0; i < 4; i++)
                pre[i] = __ldg((const float4*)(W + (size_t)(k0 + 32 + wr + i * 8) * HID + wcq));
        }
#pragma unroll
        for (int ks = 0; ks < 32; ks += 8) {
            unsigned af[4][4], bf[4][2];
#pragma unroll
            for (int mt = 0; mt < 4; mt++) {
                const unsigned* p = z1s + (warpM + mt * 16 + gid) * SZ + k0 + ks + tig;
                af[mt][0] = p[0];
                af[mt][1] = p[8 * SZ];
                af[mt][2] = p[4];
                af[mt][3] = p[8 * SZ + 4];
            }
#pragma unroll
            for (int nt = 0; nt < 4; nt++) {
                const unsigned* p = Ws + (ks + tig) * SW + warpN + nt * 8 + gid;
                bf[nt][0] = p[0];
                bf[nt][1] = p[4 * SW];
            }
#pragma unroll
            for (int mt = 0; mt < 4; mt++)
#pragma unroll
                for (int nt = 0; nt < 4; nt++)
                    mma8(acc[mt][nt], af[mt][0], af[mt][1], af[mt][2], af[mt][3],
                         bf[nt][0], bf[nt][1]);
        }
        __syncthreads();
    }
}

// ---- fused node-layer MLP: z2 = relu(relu(agg@W1+b1)@W2+b2), + BN stats ----
__global__ __launch_bounds__(256, 2)
void gin_mlp_kernel(const float* __restrict__ agg,
                    const float* __restrict__ W1, const float* __restrict__ b1,
                    const float* __restrict__ W2, const float* __restrict__ b2,
                    float* __restrict__ z2out, float* __restrict__ stats) {
    extern __shared__ unsigned dsm[];
    unsigned* z1s = dsm;
    unsigned* Ws  = dsm + 128 * SZ;
    int tid = threadIdx.x;
    int warp = tid >> 5, lane = tid & 31;
    int gid = lane >> 2, tig = lane & 3;
    int row0 = blockIdx.x * 128;
    int warpM = (warp >> 2) * 64;
    int warpN = (warp & 3) * 32;

    {
        unsigned sZ = (unsigned)__cvta_generic_to_shared(z1s);
        int r = tid >> 1, cb = (tid & 1) * 64;
        int gr = row0 + r;
        int ok = (gr < N_NODES) ? 16 : 0;
        const float* src = agg + (size_t)(ok ? gr : 0) * HID + cb;
#pragma unroll
        for (int c = 0; c < 16; c++)
            cp16(sZ + (unsigned)(r * SZ + cb + c * 4) * 4u, src + c * 4, ok);
        CP_COMMIT();
        CP_WAIT0();
    }
    __syncthreads();

    float acc[4][4][4];

    gemm128(z1s, Ws, W1, acc, tid, warpM, warpN, gid, tig);
#pragma unroll
    for (int mt = 0; mt < 4; mt++)
#pragma unroll
        for (int half = 0; half < 2; half++) {
            int r = warpM + mt * 16 + gid + half * 8;
#pragma unroll
            for (int nt = 0; nt < 4; nt++) {
                int gc = warpN + nt * 8 + tig * 2;
                float vx = fmaxf(acc[mt][nt][half * 2 + 0] + __ldg(&b1[gc]), 0.f);
                float vy = fmaxf(acc[mt][nt][half * 2 + 1] + __ldg(&b1[gc + 1]), 0.f);
                z1s[r * SZ + gc]     = f2tf32(vx);
                z1s[r * SZ + gc + 1] = f2tf32(vy);
            }
        }
    __syncthreads();

    gemm128(z1s, Ws, W2, acc, tid, warpM, warpN, gid, tig);

    float* sS = (float*)Ws;
    float* sQ = sS + 128;
    if (tid < 256) ((float*)Ws)[tid] = 0.f;
    __syncthreads();

    float sumS[4][2] = {}, sumQ[4][2] = {};
#pragma unroll
    for (int mt = 0; mt < 4; mt++)
#pragma unroll
        for (int half = 0; half < 2; half++) {
            int gr = row0 + warpM + mt * 16 + gid + half * 8;
            if (gr >= N_NODES) continue;
#pragma unroll
            for (int nt = 0; nt < 4; nt++) {
                int gc = warpN + nt * 8 + tig * 2;
                float vx = fmaxf(acc[mt][nt][half * 2 + 0] + __ldg(&b2[gc]), 0.f);
                float vy = fmaxf(acc[mt][nt][half * 2 + 1] + __ldg(&b2[gc + 1]), 0.f);
                *(float2*)(z2out + (size_t)gr * HID + gc) = make_float2(vx, vy);
                sumS[nt][0] += vx; sumQ[nt][0] += vx * vx;
                sumS[nt][1] += vy; sumQ[nt][1] += vy * vy;
            }
        }
#pragma unroll
    for (int nt = 0; nt < 4; nt++) {
        int gc = warpN + nt * 8 + tig * 2;
        atomicAdd(&sS[gc],     sumS[nt][0]);
        atomicAdd(&sS[gc + 1], sumS[nt][1]);
        atomicAdd(&sQ[gc],     sumQ[nt][0]);
        atomicAdd(&sQ[gc + 1], sumQ[nt][1]);
    }
    __syncthreads();
    if (tid < 128) {
        atomicAdd(&stats[tid],       sS[tid]);
        atomicAdd(&stats[HID + tid], sQ[tid]);
    }
}

// -- WIDE P-GEMM (ldmatrix, 512 threads, warp tile 64x32): CTA 128x256, K=512 --
__global__ __launch_bounds__(512, 1)
void tf32_gemm_wide(const float* __restrict__ A, int lda,
                    const float* __restrict__ Bt,
                    float* __restrict__ C, int ldc, int M) {
    extern __shared__ float sm[];
    float* Ab[2] = { sm, sm + 128 * SA };
    float* Bb[2] = { sm + 2 * 128 * SA, sm + 2 * 128 * SA + 256 * SBT };
    int tid = threadIdx.x;
    int warp = tid >> 5, lane = tid & 31;
    int row0 = blockIdx.y * 128;
    int col0 = blockIdx.x * 256;
    int warpM = (warp >> 3) * 64;     // 2 M-positions
    int warpN = (warp & 7) * 32;      // 8 N-positions

    // ldmatrix lane address components
    int a_row = lane & 15, a_koff = (lane >> 4) * 4;
    int b_row = lane & 7, b_koff = ((lane >> 3) & 1) * 4;
    int b_nsel = (lane >> 4);

    float acc[4][4][4];
#pragma unroll
    for (int a = 0; a < 4; a++)
#pragma unroll
        for (int b = 0; b < 4; b++)
#pragma unroll
            for (int c = 0; c < 4; c++) acc[a][b][c] = 0.f;

    // prologue: tile 0 (coalesced, 512 threads)
    {
        unsigned sA = (unsigned)__cvta_generic_to_shared(Ab[0]);
        unsigned sB = (unsigned)__cvta_generic_to_shared(Bb[0]);
#pragma unroll
        for (int i = 0; i < 2; i++) {
            int f = tid + i * 512;
            int r = f >> 3, c = (f & 7) << 2;
            int gr = row0 + r;
            int ok = (gr < M) ? 16 : 0;
            cp16(sA + (unsigned)(r * SA + c) * 4u,
                 A + (size_t)(ok ? gr : 0) * lda + c, ok);
        }
#pragma unroll
        for (int i = 0; i < 4; i++) {
            int f = tid + i * 512;
            int r = f >> 3, c = (f & 7) << 2;
            cp16(sB + (unsigned)(r * SBT + c) * 4u,
                 Bt + (size_t)(col0 + r) * 512 + c, 16);
        }
        CP_COMMIT();
    }

    for (int t = 0; t < 16; t++) {
        CP_WAIT0();
        __syncthreads();
        if (t + 1 < 16) {
            int nb = (t + 1) & 1;
            int k0 = (t + 1) << 5;
            unsigned sA = (unsigned)__cvta_generic_to_shared(Ab[nb]);
            unsigned sB = (unsigned)__cvta_generic_to_shared(Bb[nb]);
#pragma unroll
            for (int i = 0; i < 2; i++) {
                int f = tid + i * 512;
                int r = f >> 3, c = (f & 7) << 2;
                int gr = row0 + r;
                int ok = (gr < M) ? 16 : 0;
                cp16(sA + (unsigned)(r * SA + c) * 4u,
                     A + (size_t)(ok ? gr : 0) * lda + k0 + c, ok);
            }
#pragma unroll
            for (int i = 0; i < 4; i++) {
                int f = tid + i * 512;
                int r = f >> 3, c = (f & 7) << 2;
                cp16(sB + (unsigned)(r * SBT + c) * 4u,
                     Bt + (size_t)(col0 + r) * 512 + k0 + c, 16);
            }
            CP_COMMIT();
        }
        unsigned aBase = (unsigned)__cvta_generic_to_shared(Ab[t & 1]);
        unsigned bBase = (unsigned)__cvta_generic_to_shared(Bb[t & 1]);
#pragma unroll
        for (int ks = 0; ks < 32; ks += 8) {
            unsigned af[4][4], bf[4][2];
#pragma unroll
            for (int mt = 0; mt < 4; mt++) {
                uint32_t addr = aBase +
                    (unsigned)((warpM + mt * 16 + a_row) * SA + ks + a_koff) * 4u;
                ldsm4(af[mt][0], af[mt][1], af[mt][2], af[mt][3], addr);
            }
#pragma unroll
            for (int j = 0; j < 2; j++) {
                uint32_t addr = bBase +
                    (unsigned)((warpN + (2 * j + b_nsel) * 8 + b_row) * SBT
                               + ks + b_koff) * 4u;
                ldsm4(bf[2 * j][0], bf[2 * j][1], bf[2 * j + 1][0], bf[2 * j + 1][1],
                      addr);
            }
#pragma unroll
            for (int mt = 0; mt < 4; mt++)
#pragma unroll
                for (int nt = 0; nt < 4; nt++)
                    mma8(acc[mt][nt], af[mt][0], af[mt][1], af[mt][2], af[mt][3],
                         bf[nt][0], bf[nt][1]);
        }
    }

    int gid = lane >> 2, tig = lane & 3;
#pragma unroll
    for (int mt = 0; mt < 4; mt++) {
#pragma unroll
        for (int half = 0; half < 2; half++) {
            int gr = row0 + warpM + mt * 16 + gid + half * 8;
            if (gr >= M) continue;
#pragma unroll
            for (int nt = 0; nt < 4; nt++) {
                int gc = col0 + warpN + nt * 8 + tig * 2;
                float2 v;
                v.x = acc[mt][nt][half * 2 + 0];
                v.y = acc[mt][nt][half * 2 + 1];
                *(float2*)(C + (size_t)gr * ldc + gc) = v;
            }
        }
    }
}

// ------------- fused edge kernel: gather + GEMM(K=256) + score dot -----------
__global__ __launch_bounds__(256, 2)
void ep_fused_kernel(const int* __restrict__ ce,
                     const float* __restrict__ P,
                     const float* __restrict__ b1,
                     const float* __restrict__ W2,
                     const float* __restrict__ b2,
                     const float* __restrict__ w3,
                     float* __restrict__ score) {
    __shared__ unsigned As[128 * SA];
    __shared__ unsigned Bs[32 * SB];
    int tid = threadIdx.x;
    int warp = tid >> 5, lane = tid & 31;
    int gid = lane >> 2, tig = lane & 3;
    int row0 = blockIdx.x * 128;
    int warpM = (warp >> 2) * 64;
    int warpN = (warp & 3) * 32;

    int rloc[4], c0v[4], c1v[4], cqv[4];
#pragma unroll
    for (int i = 0; i < 4; i++) {
        int f = tid + i * 256;
        rloc[i] = f >> 3;
        cqv[i] = (f & 7) << 2;
        int gr = row0 + rloc[i];
        if (gr < NCANDE) {
            c0v[i] = __ldg(&ce[gr]);
            c1v[i] = __ldg(&ce[NCANDE + gr]);
        } else { c0v[i] = 0; c1v[i] = 0; }
    }

    float acc[4][4][4];
#pragma unroll
    for (int a = 0; a < 4; a++)
#pragma unroll
        for (int b = 0; b < 4; b++)
#pragma unroll
            for (int c = 0; c < 4; c++) acc[a][b][c] = 0.f;

    for (int k0 = 0; k0 < 256; k0 += 32) {
#pragma unroll
        for (int i = 0; i < 4; i++) {
            int r = rloc[i], cq = cqv[i];
            float4 v = make_float4(0.f, 0.f, 0.f, 0.f);
            if (row0 + r < NCANDE) {
                float4 a = __ldg((const float4*)(P + (size_t)c0v[i] * 512 + k0 + cq));
                float4 b = __ldg((const float4*)(P + (size_t)c1v[i] * 512 + 256 + k0 + cq));
                float4 bb = __ldg((const float4*)(b1 + k0 + cq));
                v.x = fmaxf(a.x + b.x + bb.x, 0.f);
                v.y = fmaxf(a.y + b.y + bb.y, 0.f);
                v.z = fmaxf(a.z + b.z + bb.z, 0.f);
                v.w = fmaxf(a.w + b.w + bb.w, 0.f);
            }
            *(uint4*)(As + r * SA + cq) = cvt4(v);
        }
#pragma unroll
        for (int i = 0; i < 4; i++) {
            int f = tid + i * 256;
            int r = f >> 5, cq = (f & 31) << 2;
            float4 v = __ldg((const float4*)(W2 + (size_t)(k0 + r) * HID + cq));
            *(uint4*)(Bs + r * SB + cq) =
                make_uint4(__float_as_uint(v.x), __float_as_uint(v.y),
                           __float_as_uint(v.z), __float_as_uint(v.w));
        }
        __syncthreads();
#pragma unroll
        for (int ks = 0; ks < 32; ks += 8) {
            unsigned af[4][4], bf[4][2];
#pragma unroll
            for (int mt = 0; mt < 4; mt++) {
                const unsigned* p = As + (warpM + mt * 16 + gid) * SA + ks + tig;
                af[mt][0] = p[0];
                af[mt][1] = p[8 * SA];
                af[mt][2] = p[4];
                af[mt][3] = p[8 * SA + 4];
            }
#pragma unroll
            for (int nt = 0; nt < 4; nt++) {
                const unsigned* p = Bs + (ks + tig) * SB + warpN + nt * 8 + gid;
                bf[nt][0] = p[0];
                bf[nt][1] = p[4 * SB];
            }
#pragma unroll
            for (int mt = 0; mt < 4; mt++)
#pragma unroll
                for (int nt = 0; nt < 4; nt++)
                    mma8(acc[mt][nt], af[mt][0], af[mt][1], af[mt][2], af[mt][3],
                         bf[nt][0], bf[nt][1]);
        }
        __syncthreads();
    }

#pragma unroll
    for (int mt = 0; mt < 4; mt++)
#pragma unroll
        for (int half = 0; half < 2; half++) {
            int gr = row0 + warpM + mt * 16 + gid + half * 8;
            float p = 0.f;
#pragma unroll
            for (int nt = 0; nt < 4; nt++) {
                int gc = warpN + nt * 8 + tig * 2;
                float vx = fmaxf(acc[mt][nt][half * 2 + 0] + __ldg(&b2[gc]), 0.f);
                float vy = fmaxf(acc[mt][nt][half * 2 + 1] + __ldg(&b2[gc + 1]), 0.f);
                p = fmaf(vx, __ldg(&w3[gc]), p);
                p = fmaf(vy, __ldg(&w3[gc + 1]), p);
            }
            p += __shfl_xor_sync(0xffffffffu, p, 1);
            p += __shfl_xor_sync(0xffffffffu, p, 2);
            if (tig == 0 && gr < NCANDE) atomicAdd(&score[gr], p);
        }
}

__global__ void sigmoid_kernel(float* __restrict__ s, const float* __restrict__ b, int n) {
    int i = blockIdx.x * blockDim.x + threadIdx.x;
    if (i < n) s[i] = 1.f / (1.f + expf(-(s[i] + b[0])));
}

// ------------------------------ batch norm apply ------------------------------
__global__ void bn_apply_kernel(const float* __restrict__ Z,
                                const float* __restrict__ stats,
                                const float* __restrict__ gamma,
                                const float* __restrict__ beta,
                                float* __restrict__ out, int ostride) {
    int idx = blockIdx.x * blockDim.x + threadIdx.x;
    if (idx >= N_NODES * HID) return;
    int row = idx / HID, col = idx - row * HID;
    float inv_n = 1.f / (float)N_NODES;
    float mu = stats[col] * inv_n;
    float var = stats[HID + col] * inv_n - mu * mu;
    float scale = rsqrtf(var + BN_EPSF) * gamma[col];
    out[(size_t)row * ostride + col] = rtf((Z[idx] - mu) * scale + beta[col]);
}

// ------------------------------- pooling -------------------------------------
#define POOL_ROWS 1024
__global__ void pool_sum_kernel(const float* __restrict__ emb,
                                const int* __restrict__ batch,
                                float* __restrict__ gsum) {
    int col = blockIdx.y * 128 + threadIdx.x;
    int r0 = blockIdx.x * POOL_ROWS;
    int r1 = min(r0 + POOL_ROWS, N_NODES);
    float acc = 0.f;
    int cur = batch[r0];
    for (int r = r0; r < r1; r++) {
        int b = batch[r];
        if (b != cur) {
            atomicAdd(&gsum[(size_t)cur * EMBW + col], acc);
            acc = 0.f; cur = b;
        }
        acc += emb[(size_t)r * EMBW + col];
    }
    atomicAdd(&gsum[(size_t)cur * EMBW + col], acc);
}

__global__ void count_kernel(const int* __restrict__ batch, float* __restrict__ cnt) {
    __shared__ int hist[N_GRAPH];
    int tid = threadIdx.x;
    if (tid < N_GRAPH) hist[tid] = 0;
    __syncthreads();
    for (int i = blockIdx.x * blockDim.x + tid; i < N_NODES; i += gridDim.x * blockDim.x)
        atomicAdd(&hist[batch[i]], 1);
    __syncthreads();
    if (tid < N_GRAPH && hist[tid]) atomicAdd(&cnt[tid], (float)hist[tid]);
}

__global__ void pool_div_kernel(float* __restrict__ gsum, const float* __restrict__ cnt) {
    int i = blockIdx.x * blockDim.x + threadIdx.x;
    if (i >= N_GRAPH * EMBW) return;
    int g = i / EMBW;
    gsum[i] = gsum[i] / fmaxf(cnt[g], 1.f);
}

// ------------------------- small MLP (classifier) -----------------------------
__global__ void small_mlp_kernel(const float* __restrict__ A,
                                 const float* __restrict__ B,
                                 const float* __restrict__ bias,
                                 float* __restrict__ C,
                                 int M, int N, int K, int relu) {
    int idx = blockIdx.x * blockDim.x + threadIdx.x;
    if (idx >= M * N) return;
    int i = idx / N, j = idx - i * N;
    float s = bias[j];
    const float* a = A + (size_t)i * K;
    for (int k = 0; k < K; k++) s = fmaf(a[k], B[(size_t)k * N + j], s);
    if (relu) s = fmaxf(s, 0.f);
    C[idx] = s;
}

__global__ void logsoftmax_kernel(const float* __restrict__ in, float* __restrict__ out) {
    int g = blockIdx.x;
    int lane = threadIdx.x;
    float v = (lane < NCLS) ? in[g * NCLS + lane] : -INFINITY;
    float m = v;
#pragma unroll
    for (int o = 16; o > 0; o >>= 1) m = fmaxf(m, __shfl_xor_sync(0xffffffffu, m, o));
    float e = (lane < NCLS) ? expf(v - m) : 0.f;
    float s = e;
#pragma unroll
    for (int o = 16; o > 0; o >>= 1) s += __shfl_xor_sync(0xffffffffu, s, o);
    if (lane < NCLS) out[g * NCLS + lane] = v - m - logf(s);
}

// --------------------------------- host --------------------------------------
static void* sym_addr(const void* sym) {
    void* p = nullptr;
    cudaGetSymbolAddress(&p, sym);
    return p;
}

extern "C" void kernel_launch(void* const* d_in, const int* in_sizes, int n_in,
                              void* d_out, int out_size) {
    (void)n_in; (void)out_size;
    const float *x, *cW1, *cb1, *cW2, *cb2, *cgamma, *cbeta, *ceps;
    const float *ncW1, *ncb1, *ncW2, *ncb2, *ncW3, *ncb3, *ncW4, *ncb4;
    const float *epW1, *epb1, *epW2, *epb2, *epW3, *epb3;
    const int *edge_index, *batch, *cand;
    bool dict_order = (in_sizes[1] == 2 * N_EDGES);
    if (dict_order) {
        x          = (const float*)d_in[0];
        edge_index = (const int*)  d_in[1];
        batch      = (const int*)  d_in[2];
        cand       = (const int*)  d_in[3];
        cW1 = (const float*)d_in[4];  cb1 = (const float*)d_in[5];
        cW2 = (const float*)d_in[6];  cb2 = (const float*)d_in[7];
        cgamma = (const float*)d_in[8]; cbeta = (const float*)d_in[9];
        ceps = (const float*)d_in[10];
        ncW1 = (const float*)d_in[11]; ncb1 = (const float*)d_in[12];
        ncW2 = (const float*)d_in[13]; ncb2 = (const float*)d_in[14];
        ncW3 = (const float*)d_in[15]; ncb3 = (const float*)d_in[16];
        ncW4 = (const float*)d_in[17]; ncb4 = (const float*)d_in[18];
        epW1 = (const float*)d_in[19]; epb1 = (const float*)d_in[20];
        epW2 = (const float*)d_in[21]; epb2 = (const float*)d_in[22];
        epW3 = (const float*)d_in[23]; epb3 = (const float*)d_in[24];
    } else {
        x = (const float*)d_in[0];
        cW1 = (const float*)d_in[1];  cb1 = (const float*)d_in[2];
        cW2 = (const float*)d_in[3];  cb2 = (const float*)d_in[4];
        cgamma = (const float*)d_in[5]; cbeta = (const float*)d_in[6];
        ceps = (const float*)d_in[7];
        ncW1 = (const float*)d_in[8];  ncb1 = (const float*)d_in[9];
        ncW2 = (const float*)d_in[10]; ncb2 = (const float*)d_in[11];
        ncW3 = (const float*)d_in[12]; ncb3 = (const float*)d_in[13];
        ncW4 = (const float*)d_in[14]; ncb4 = (const float*)d_in[15];
        epW1 = (const float*)d_in[16]; epb1 = (const float*)d_in[17];
        epW2 = (const float*)d_in[18]; epb2 = (const float*)d_in[19];
        epW3 = (const float*)d_in[20]; epb3 = (const float*)d_in[21];
        edge_index = (const int*)d_in[22];
        batch      = (const int*)d_in[23];
        cand       = (const int*)d_in[24];
    }
    float* out = (float*)d_out;

    float* p_emb  = (float*)sym_addr(g_emb);
    float* p_agg  = (float*)sym_addr(g_agg);
    float* p_z2   = (float*)sym_addr(g_z2);
    float* p_P    = (float*)sym_addr(g_P);
    float* p_st   = (float*)sym_addr(g_stats);
    float* p_gemb = (float*)sym_addr(g_gemb);
    float* p_cnt  = (float*)sym_addr(g_cnt);
    float* p_t1   = (float*)sym_addr(g_t1);
    float* p_t2   = (float*)sym_addr(g_t2);
    float* p_t3   = (float*)sym_addr(g_t3);
    float* p_lg   = (float*)sym_addr(g_logits);
    float* p_wc1  = (float*)sym_addr(g_wc1);
    float* p_wc2  = (float*)sym_addr(g_wc2);
    float* p_w1t  = (float*)sym_addr(g_w1t);
    float* p_w2   = (float*)sym_addr(g_w2);
    int* p_deg  = (int*)sym_addr(g_deg);
    int* p_off  = (int*)sym_addr(g_off);
    int* p_pos  = (int*)sym_addr(g_pos);
    int* p_csr  = (int*)sym_addr(g_csr);
    int* p_bsum = (int*)sym_addr(g_bsum);

    static bool attr_done = false;
    if (!attr_done) {
        cudaFuncSetAttribute(gin_mlp_kernel,
                             cudaFuncAttributeMaxDynamicSharedMemorySize, GIN_SMEM);
        cudaFuncSetAttribute(tf32_gemm_wide,
                             cudaFuncAttributeMaxDynamicSharedMemorySize, WIDE_SMEM);
        attr_done = true;
    }

    const int T = 256;
    const int NODE_BLKS = (N_NODES + 127) / 128;
    const int CAND_BLKS = (NCANDE + 127) / 128;
    const int nScanBlocks = (N_NODES + SCAN_B - 1) / SCAN_B;

    // ============ weight prep ============
    round_weights_kernel<<<(NLAY * HID * HID + T - 1) / T, T>>>(cW1, cW2, epW2,
                                                                p_wc1, p_wc2, p_w2);
    build_w1t_kernel<<<(512 * 512 + T - 1) / T, T>>>(epW1, p_w1t);

    // ================= CSR build =================
    zeroi_kernel<<<(N_NODES + T - 1) / T, T>>>(p_deg, N_NODES);
    hist_kernel<<<(N_EDGES + T - 1) / T, T>>>(edge_index, p_deg);
    scan_block_kernel<<<nScanBlocks, SCAN_B>>>(p_deg, p_off, p_bsum, N_NODES);
    scan_bsum_kernel<<<1, 128>>>(p_bsum, nScanBlocks);
    scan_add_kernel<<<(N_NODES + T) / T, T>>>(p_off, p_bsum, p_pos, N_NODES);
    csr_fill_kernel<<<(N_EDGES + T - 1) / T, T>>>(edge_index, p_pos, p_csr);

    // ================= GIN layers =================
    for (int l = 0; l < NLAY; l++) {
        const float* h = (l == 0) ? x : (p_emb + (l - 1) * HID);
        int hstride = (l == 0) ? HID : EMBW;

        gin_gather_kernel<<<(N_NODES * 32 + T - 1) / T, T>>>(p_off, p_csr, h, hstride,
                                                             ceps, l, p_agg);
        zero_kernel<<<1, 256>>>(p_st, 2 * HID);
        gin_mlp_kernel<<<NODE_BLKS, 256, GIN_SMEM>>>(
            p_agg,
            p_wc1 + (size_t)l * HID * HID, cb1 + l * HID,
            p_wc2 + (size_t)l * HID * HID, cb2 + l * HID,
            p_z2, p_st);
        bn_apply_kernel<<<(N_NODES * HID + T - 1) / T, T>>>(
            p_z2, p_st, cgamma + l * HID, cbeta + l * HID, p_emb + l * HID, EMBW);
    }

    // ================= global mean pool =================
    zero_kernel<<<(N_GRAPH * EMBW + T - 1) / T, T>>>(p_gemb, N_GRAPH * EMBW);
    zero_kernel<<<1, 64>>>(p_cnt, N_GRAPH);
    {
        dim3 pg((N_NODES + POOL_ROWS - 1) / POOL_ROWS, EMBW / 128);
        pool_sum_kernel<<<pg, 128>>>(p_emb, batch, p_gemb);
    }
    count_kernel<<<128, 256>>>(batch, p_cnt);
    pool_div_kernel<<<(N_GRAPH * EMBW + T - 1) / T, T>>>(p_gemb, p_cnt);

    // ================= node classifier =================
    small_mlp_kernel<<<(N_GRAPH * 256 + T - 1) / T, T>>>(p_gemb, ncW1, ncb1, p_t1,
                                                         N_GRAPH, 256, EMBW, 1);
    small_mlp_kernel<<<(N_GRAPH * 128 + T - 1) / T, T>>>(p_t1, ncW2, ncb2, p_t2,
                                                         N_GRAPH, 128, 256, 1);
    small_mlp_kernel<<<(N_GRAPH * 128 + T - 1) / T, T>>>(p_t2, ncW3, ncb3, p_t3,
                                                         N_GRAPH, 128, 128, 1);
    small_mlp_kernel<<<(N_GRAPH * NCLS + T - 1) / T, T>>>(p_t3, ncW4, ncb4, p_lg,
                                                          N_GRAPH, NCLS, 128, 0);
    logsoftmax_kernel<<<N_GRAPH, 32>>>(p_lg, out);

    // ================= edge predictor =================
    {
        dim3 wg(2, NODE_BLKS);    // N=512 in two 256-wide tiles
        tf32_gemm_wide<<<wg, 512, WIDE_SMEM>>>(p_emb, EMBW, p_w1t, p_P, 512, N_NODES);
    }
    float* scores = out + N_GRAPH * NCLS;
    zero_kernel<<<(NCANDE + T - 1) / T, T>>>(scores, NCANDE);
    ep_fused_kernel<<<CAND_BLKS, 256>>>(cand, p_P, epb1, p_w2, epb2, epW3, scores);
    sigmoid_kernel<<<(NCANDE + T - 1) / T, T>>>(scores, epb3, NCANDE);
}

// round 15
// speedup vs baseline: 1.0136x; 1.0070x over previous
#include <cuda_runtime.h>
#include <math.h>
#include <stdint.h>

#define N_NODES 100000
#define N_EDGES 1600000
#define N_GRAPH 64
#define HID     128
#define NLAY    4
#define NCLS    16
#define NCANDE  100000
#define EMBW    512           // NLAY*HID
#define BN_EPSF 1e-5f

// ------------------------- persistent device scratch -------------------------
__device__ float g_emb[(size_t)N_NODES * EMBW];
__device__ float g_agg[(size_t)N_NODES * HID];
__device__ float g_z2 [(size_t)N_NODES * HID];
__device__ float g_P  [(size_t)NCANDE * 512];
__device__ float g_stats[2 * HID];
__device__ float g_gemb[N_GRAPH * EMBW];
__device__ float g_cnt [N_GRAPH];
__device__ float g_t1[N_GRAPH * 256];
__device__ float g_t2[N_GRAPH * 128];
__device__ float g_t3[N_GRAPH * 128];
__device__ float g_logits[N_GRAPH * NCLS];
// pre-rounded (tf32-representable) weights
__device__ float g_wc1[NLAY * HID * HID];
__device__ float g_wc2[NLAY * HID * HID];
__device__ float g_w1t[512 * 512];      // combined epW1, transposed [N=512][K=512]
__device__ float g_w2 [256 * 128];
// CSR scratch
__device__ int g_deg[N_NODES];
__device__ int g_off[N_NODES + 1];
__device__ int g_pos[N_NODES];
__device__ int g_csr[N_EDGES];
__device__ int g_bsum[128];

// ------------------------------- small utils --------------------------------
__global__ void zero_kernel(float* p, int n) {
    int i = blockIdx.x * blockDim.x + threadIdx.x;
    if (i < n) p[i] = 0.f;
}
__global__ void zeroi_kernel(int* p, int n) {
    int i = blockIdx.x * blockDim.x + threadIdx.x;
    if (i < n) p[i] = 0;
}

// ----------------------------- tf32 helpers ----------------------------------
__device__ __forceinline__ unsigned f2tf32(float f) {
    unsigned r;
    asm("cvt.rna.tf32.f32 %0, %1;" : "=r"(r) : "f"(f));
    return r;
}
__device__ __forceinline__ float rtf(float f) { return __uint_as_float(f2tf32(f)); }
__device__ __forceinline__ uint4 cvt4(float4 v) {
    uint4 w;
    w.x = f2tf32(v.x); w.y = f2tf32(v.y); w.z = f2tf32(v.z); w.w = f2tf32(v.w);
    return w;
}
__device__ __forceinline__ void mma8(float* d, unsigned a0, unsigned a1, unsigned a2,
                                     unsigned a3, unsigned b0, unsigned b1) {
    asm volatile(
        "mma.sync.aligned.m16n8k8.row.col.f32.tf32.tf32.f32 "
        "{%0,%1,%2,%3}, {%4,%5,%6,%7}, {%8,%9}, {%0,%1,%2,%3};"
        : "+f"(d[0]), "+f"(d[1]), "+f"(d[2]), "+f"(d[3])
        : "r"(a0), "r"(a1), "r"(a2), "r"(a3), "r"(b0), "r"(b1));
}
__device__ __forceinline__ void cp16(unsigned sdst, const void* gsrc, int srcbytes) {
    asm volatile("cp.async.ca.shared.global [%0], [%1], 16, %2;"
                 :: "r"(sdst), "l"(gsrc), "r"(srcbytes));
}
#define CP_COMMIT() asm volatile("cp.async.commit_group;")
#define CP_WAIT0()  asm volatile("cp.async.wait_group 0;" ::: "memory")

// ldmatrix: reg i = matrix i; lane l gets word (row l>>2, chunk l&3) of each.
__device__ __forceinline__ void ldsm4(unsigned& r0, unsigned& r1, unsigned& r2,
                                      unsigned& r3, uint32_t addr) {
    asm volatile("ldmatrix.sync.aligned.m8n8.x4.shared.b16 {%0,%1,%2,%3}, [%4];"
                 : "=r"(r0), "=r"(r1), "=r"(r2), "=r"(r3) : "r"(addr));
}

// round weights once (makes HW tf32 truncation exact == cvt.rna semantics)
__global__ void round_weights_kernel(const float* __restrict__ cW1,
                                     const float* __restrict__ cW2,
                                     const float* __restrict__ epW2,
                                     float* __restrict__ wc1, float* __restrict__ wc2,
                                     float* __restrict__ w2) {
    int i = blockIdx.x * blockDim.x + threadIdx.x;
    if (i < NLAY * HID * HID) { wc1[i] = rtf(cW1[i]); wc2[i] = rtf(cW2[i]); }
    if (i < 256 * 128)  w2[i] = rtf(epW2[i]);
}

// build combined transposed [N=512][K=512] epW1 (halves side by side in N)
__global__ void build_w1t_kernel(const float* __restrict__ epW1, float* __restrict__ w1t) {
    int i = blockIdx.x * blockDim.x + threadIdx.x;   // i = n*512 + k
    if (i >= 512 * 512) return;
    int n = i >> 9, k = i & 511;
    float v = (n < 256) ? epW1[(size_t)k * 256 + n]
                        : epW1[(size_t)(512 + k) * 256 + (n - 256)];
    w1t[i] = rtf(v);
}

// ------------------------------ CSR build ------------------------------------
__global__ void hist_kernel(const int* __restrict__ ei, int* __restrict__ deg) {
    int e = blockIdx.x * blockDim.x + threadIdx.x;
    if (e < N_EDGES) atomicAdd(&deg[ei[N_EDGES + e]], 1);
}

#define SCAN_B 1024
__global__ void scan_block_kernel(const int* __restrict__ deg, int* __restrict__ off,
                                  int* __restrict__ bsum, int n) {
    __shared__ int sh[SCAN_B];
    int g = blockIdx.x * SCAN_B + threadIdx.x;
    int v = (g < n) ? deg[g] : 0;
    sh[threadIdx.x] = v;
    __syncthreads();
#pragma unroll
    for (int o = 1; o < SCAN_B; o <<= 1) {
        int t = (threadIdx.x >= o) ? sh[threadIdx.x - o] : 0;
        __syncthreads();
        sh[threadIdx.x] += t;
        __syncthreads();
    }
    if (g < n) off[g] = sh[threadIdx.x] - v;
    if (threadIdx.x == SCAN_B - 1) bsum[blockIdx.x] = sh[SCAN_B - 1];
}

__global__ void scan_bsum_kernel(int* __restrict__ bsum, int nb) {
    __shared__ int sh[128];
    int v = (threadIdx.x < nb) ? bsum[threadIdx.x] : 0;
    sh[threadIdx.x] = v;
    __syncthreads();
#pragma unroll
    for (int o = 1; o < 128; o <<= 1) {
        int t = (threadIdx.x >= o) ? sh[threadIdx.x - o] : 0;
        __syncthreads();
        sh[threadIdx.x] += t;
        __syncthreads();
    }
    if (threadIdx.x < nb) bsum[threadIdx.x] = sh[threadIdx.x] - v;
}

__global__ void scan_add_kernel(int* __restrict__ off, const int* __restrict__ bsum,
                                int* __restrict__ pos, int n) {
    int g = blockIdx.x * blockDim.x + threadIdx.x;
    if (g < n) {
        int o = off[g] + bsum[g / SCAN_B];
        off[g] = o;
        pos[g] = o;
    }
    if (g == n) off[n] = N_EDGES;
}

__global__ void csr_fill_kernel(const int* __restrict__ ei, int* __restrict__ pos,
                                int* __restrict__ csr) {
    int e = blockIdx.x * blockDim.x + threadIdx.x;
    if (e >= N_EDGES) return;
    int dst = ei[N_EDGES + e];
    int p = atomicAdd(&pos[dst], 1);
    csr[p] = ei[e];
}

// --------- GIN aggregation: warp-per-node gather (+ zero stats by block 0) ----
__global__ void gin_gather_kernel(const int* __restrict__ off,
                                  const int* __restrict__ csr,
                                  const float* __restrict__ h, int hstride,
                                  const float* __restrict__ ceps, int layer,
                                  float* __restrict__ agg,
                                  float* __restrict__ stats) {
    if (blockIdx.x == 0 && threadIdx.x < 2 * HID) stats[threadIdx.x] = 0.f;
    int node = (blockIdx.x * blockDim.x + threadIdx.x) >> 5;
    int lane = threadIdx.x & 31;
    if (node >= N_NODES) return;
    int s = off[node], e = off[node + 1];
    float c = 1.f + __ldg(&ceps[layer]);
    float4 acc = __ldg((const float4*)(h + (size_t)node * hstride) + lane);
    acc.x *= c; acc.y *= c; acc.z *= c; acc.w *= c;
    for (int i = s; i < e; i++) {
        int src = __ldg(&csr[i]);
        float4 v = __ldg((const float4*)(h + (size_t)src * hstride) + lane);
        acc.x += v.x; acc.y += v.y; acc.z += v.z; acc.w += v.w;
    }
    acc.x = rtf(acc.x); acc.y = rtf(acc.y); acc.z = rtf(acc.z); acc.w = rtf(acc.w);
    *((float4*)(agg + (size_t)node * HID) + lane) = acc;
}

#define SA  36
#define SZ  132
#define SW  136
#define SB  136
#define SBT 36
#define GIN_SMEM ((128 * SZ + 32 * SW) * 4)                 // 84992 B -> 2 CTA/SM
#define WIDE_SMEM ((2 * 128 * SA + 2 * 256 * SBT) * 4)      // 110592 B

// ---- GEMM phase: A persistent in smem (128xSZ), weight chunks reg-prefetched --
__device__ __forceinline__ void gemm128(const unsigned* __restrict__ z1s,
                                        unsigned* __restrict__ Ws,
                                        const float* __restrict__ W,
                                        float acc[4][4][4],
                                        int tid, int warpM, int warpN,
                                        int gid, int tig) {
#pragma unroll
    for (int a = 0; a < 4; a++)
#pragma unroll
        for (int b = 0; b < 4; b++)
#pragma unroll
            for (int c = 0; c < 4; c++) acc[a][b][c] = 0.f;

    int wr = tid >> 5, wcq = (tid & 31) << 2;
    float4 pre[4];
#pragma unroll
    for (int i = 0; i < 4; i++)
        pre[i] = __ldg((const float4*)(W + (size_t)(wr + i * 8) * HID + wcq));

    for (int k0 = 0; k0 < 128; k0 += 32) {
#pragma unroll
        for (int i = 0; i < 4; i++)
            *(uint4*)(Ws + (wr + i * 8) * SW + wcq) = cvt4(pre[i]);
        __syncthreads();
        if (k0 < 96) {
#pragma unroll
            for (int i = 0; i < 4; i++)
                pre[i] = __ldg((const float4*)(W + (size_t)(k0 + 32 + wr + i * 8) * HID + wcq));
        }
#pragma unroll
        for (int ks = 0; ks < 32; ks += 8) {
            unsigned af[4][4], bf[4][2];
#pragma unroll
            for (int mt = 0; mt < 4; mt++) {
                const unsigned* p = z1s + (warpM + mt * 16 + gid) * SZ + k0 + ks + tig;
                af[mt][0] = p[0];
                af[mt][1] = p[8 * SZ];
                af[mt][2] = p[4];
                af[mt][3] = p[8 * SZ + 4];
            }
#pragma unroll
            for (int nt = 0; nt < 4; nt++) {
                const unsigned* p = Ws + (ks + tig) * SW + warpN + nt * 8 + gid;
                bf[nt][0] = p[0];
                bf[nt][1] = p[4 * SW];
            }
#pragma unroll
            for (int mt = 0; mt < 4; mt++)
#pragma unroll
                for (int nt = 0; nt < 4; nt++)
                    mma8(acc[mt][nt], af[mt][0], af[mt][1], af[mt][2], af[mt][3],
                         bf[nt][0], bf[nt][1]);
        }
        __syncthreads();
    }
}

// ---- fused node-layer MLP: z2 = relu(relu(agg@W1+b1)@W2+b2), + BN stats ----
__global__ __launch_bounds__(256, 2)
void gin_mlp_kernel(const float* __restrict__ agg,
                    const float* __restrict__ W1, const float* __restrict__ b1,
                    const float* __restrict__ W2, const float* __restrict__ b2,
                    float* __restrict__ z2out, float* __restrict__ stats) {
    extern __shared__ unsigned dsm[];
    unsigned* z1s = dsm;
    unsigned* Ws  = dsm + 128 * SZ;
    int tid = threadIdx.x;
    int warp = tid >> 5, lane = tid & 31;
    int gid = lane >> 2, tig = lane & 3;
    int row0 = blockIdx.x * 128;
    int warpM = (warp >> 2) * 64;
    int warpN = (warp & 3) * 32;

    {
        unsigned sZ = (unsigned)__cvta_generic_to_shared(z1s);
        int r = tid >> 1, cb = (tid & 1) * 64;
        int gr = row0 + r;
        int ok = (gr < N_NODES) ? 16 : 0;
        const float* src = agg + (size_t)(ok ? gr : 0) * HID + cb;
#pragma unroll
        for (int c = 0; c < 16; c++)
            cp16(sZ + (unsigned)(r * SZ + cb + c * 4) * 4u, src + c * 4, ok);
        CP_COMMIT();
        CP_WAIT0();
    }
    __syncthreads();

    float acc[4][4][4];

    gemm128(z1s, Ws, W1, acc, tid, warpM, warpN, gid, tig);
#pragma unroll
    for (int mt = 0; mt < 4; mt++)
#pragma unroll
        for (int half = 0; half < 2; half++) {
            int r = warpM + mt * 16 + gid + half * 8;
#pragma unroll
            for (int nt = 0; nt < 4; nt++) {
                int gc = warpN + nt * 8 + tig * 2;
                float vx = fmaxf(acc[mt][nt][half * 2 + 0] + __ldg(&b1[gc]), 0.f);
                float vy = fmaxf(acc[mt][nt][half * 2 + 1] + __ldg(&b1[gc + 1]), 0.f);
                z1s[r * SZ + gc]     = f2tf32(vx);
                z1s[r * SZ + gc + 1] = f2tf32(vy);
            }
        }
    __syncthreads();

    gemm128(z1s, Ws, W2, acc, tid, warpM, warpN, gid, tig);

    float* sS = (float*)Ws;
    float* sQ = sS + 128;
    if (tid < 256) ((float*)Ws)[tid] = 0.f;
    __syncthreads();

    float sumS[4][2] = {}, sumQ[4][2] = {};
#pragma unroll
    for (int mt = 0; mt < 4; mt++)
#pragma unroll
        for (int half = 0; half < 2; half++) {
            int gr = row0 + warpM + mt * 16 + gid + half * 8;
            if (gr >= N_NODES) continue;
#pragma unroll
            for (int nt = 0; nt < 4; nt++) {
                int gc = warpN + nt * 8 + tig * 2;
                float vx = fmaxf(acc[mt][nt][half * 2 + 0] + __ldg(&b2[gc]), 0.f);
                float vy = fmaxf(acc[mt][nt][half * 2 + 1] + __ldg(&b2[gc + 1]), 0.f);
                *(float2*)(z2out + (size_t)gr * HID + gc) = make_float2(vx, vy);
                sumS[nt][0] += vx; sumQ[nt][0] += vx * vx;
                sumS[nt][1] += vy; sumQ[nt][1] += vy * vy;
            }
        }
#pragma unroll
    for (int nt = 0; nt < 4; nt++) {
        int gc = warpN + nt * 8 + tig * 2;
        atomicAdd(&sS[gc],     sumS[nt][0]);
        atomicAdd(&sS[gc + 1], sumS[nt][1]);
        atomicAdd(&sQ[gc],     sumQ[nt][0]);
        atomicAdd(&sQ[gc + 1], sumQ[nt][1]);
    }
    __syncthreads();
    if (tid < 128) {
        atomicAdd(&stats[tid],       sS[tid]);
        atomicAdd(&stats[HID + tid], sQ[tid]);
    }
}

// ------- WIDE P-GEMM with ldmatrix (coalesced staging): 128x256, K=512 -------
__global__ __launch_bounds__(256, 1)
void tf32_gemm_wide(const float* __restrict__ A, int lda,
                    const float* __restrict__ Bt,
                    float* __restrict__ C, int ldc, int M) {
    extern __shared__ float sm[];
    float* Ab[2] = { sm, sm + 128 * SA };
    float* Bb[2] = { sm + 2 * 128 * SA, sm + 2 * 128 * SA + 256 * SBT };
    int tid = threadIdx.x;
    int warp = tid >> 5, lane = tid & 31;
    int row0 = blockIdx.y * 128;
    int col0 = blockIdx.x * 256;
    int warpM = (warp >> 2) * 64;
    int warpN = (warp & 3) * 64;

    int ar = tid >> 3, acq = (tid & 7) << 2;

    int a_row = lane & 15, a_koff = (lane >> 4) * 4;
    int b_row = lane & 7, b_koff = ((lane >> 3) & 1) * 4;
    int b_nsel = (lane >> 4);

    float acc[4][8][4];
#pragma unroll
    for (int a = 0; a < 4; a++)
#pragma unroll
        for (int b = 0; b < 8; b++)
#pragma unroll
            for (int c = 0; c < 4; c++) acc[a][b][c] = 0.f;

    {
        unsigned sA = (unsigned)__cvta_generic_to_shared(Ab[0]);
        unsigned sB = (unsigned)__cvta_generic_to_shared(Bb[0]);
#pragma unroll
        for (int i = 0; i < 4; i++) {
            int r = ar + i * 32;
            int gr = row0 + r;
            int ok = (gr < M) ? 16 : 0;
            cp16(sA + (unsigned)(r * SA + acq) * 4u,
                 A + (size_t)(ok ? gr : 0) * lda + acq, ok);
        }
#pragma unroll
        for (int i = 0; i < 8; i++) {
            int f = tid + i * 256;
            int r = f >> 3, c = (f & 7) << 2;
            cp16(sB + (unsigned)(r * SBT + c) * 4u,
                 Bt + (size_t)(col0 + r) * 512 + c, 16);
        }
        CP_COMMIT();
    }

    for (int t = 0; t < 16; t++) {
        CP_WAIT0();
        __syncthreads();
        if (t + 1 < 16) {
            int nb = (t + 1) & 1;
            int k0 = (t + 1) << 5;
            unsigned sA = (unsigned)__cvta_generic_to_shared(Ab[nb]);
            unsigned sB = (unsigned)__cvta_generic_to_shared(Bb[nb]);
#pragma unroll
            for (int i = 0; i < 4; i++) {
                int r = ar + i * 32;
                int gr = row0 + r;
                int ok = (gr < M) ? 16 : 0;
                cp16(sA + (unsigned)(r * SA + acq) * 4u,
                     A + (size_t)(ok ? gr : 0) * lda + k0 + acq, ok);
            }
#pragma unroll
            for (int i = 0; i < 8; i++) {
                int f = tid + i * 256;
                int r = f >> 3, c = (f & 7) << 2;
                cp16(sB + (unsigned)(r * SBT + c) * 4u,
                     Bt + (size_t)(col0 + r) * 512 + k0 + c, 16);
            }
            CP_COMMIT();
        }
        unsigned aBase = (unsigned)__cvta_generic_to_shared(Ab[t & 1]);
        unsigned bBase = (unsigned)__cvta_generic_to_shared(Bb[t & 1]);
#pragma unroll
        for (int ks = 0; ks < 32; ks += 8) {
            unsigned af[4][4], bf[8][2];
#pragma unroll
            for (int mt = 0; mt < 4; mt++) {
                uint32_t addr = aBase +
                    (unsigned)((warpM + mt * 16 + a_row) * SA + ks + a_koff) * 4u;
                ldsm4(af[mt][0], af[mt][1], af[mt][2], af[mt][3], addr);
            }
#pragma unroll
            for (int j = 0; j < 4; j++) {
                uint32_t addr = bBase +
                    (unsigned)((warpN + (2 * j + b_nsel) * 8 + b_row) * SBT
                               + ks + b_koff) * 4u;
                ldsm4(bf[2 * j][0], bf[2 * j][1], bf[2 * j + 1][0], bf[2 * j + 1][1],
                      addr);
            }
#pragma unroll
            for (int mt = 0; mt < 4; mt++)
#pragma unroll
                for (int nt = 0; nt < 8; nt++)
                    mma8(acc[mt][nt], af[mt][0], af[mt][1], af[mt][2], af[mt][3],
                         bf[nt][0], bf[nt][1]);
        }
    }

    int gid = lane >> 2, tig = lane & 3;
#pragma unroll
    for (int mt = 0; mt < 4; mt++) {
#pragma unroll
        for (int half = 0; half < 2; half++) {
            int gr = row0 + warpM + mt * 16 + gid + half * 8;
            if (gr >= M) continue;
#pragma unroll
            for (int nt = 0; nt < 8; nt++) {
                int gc = col0 + warpN + nt * 8 + tig * 2;
                float2 v;
                v.x = acc[mt][nt][half * 2 + 0];
                v.y = acc[mt][nt][half * 2 + 1];
                *(float2*)(C + (size_t)gr * ldc + gc) = v;
            }
        }
    }
}

// -- fused edge kernel: gather + GEMM(K=256) + score dot + smem reduce+sigmoid --
__global__ __launch_bounds__(256, 2)
void ep_fused_kernel(const int* __restrict__ ce,
                     const float* __restrict__ P,
                     const float* __restrict__ b1,
                     const float* __restrict__ W2,
                     const float* __restrict__ b2,
                     const float* __restrict__ w3,
                     const float* __restrict__ b3,
                     float* __restrict__ score) {
    __shared__ unsigned As[128 * SA];
    __shared__ unsigned Bs[32 * SB];
    int tid = threadIdx.x;
    int warp = tid >> 5, lane = tid & 31;
    int gid = lane >> 2, tig = lane & 3;
    int row0 = blockIdx.x * 128;
    int warpM = (warp >> 2) * 64;
    int warpN = (warp & 3) * 32;

    int rloc[4], c0v[4], c1v[4], cqv[4];
#pragma unroll
    for (int i = 0; i < 4; i++) {
        int f = tid + i * 256;
        rloc[i] = f >> 3;
        cqv[i] = (f & 7) << 2;
        int gr = row0 + rloc[i];
        if (gr < NCANDE) {
            c0v[i] = __ldg(&ce[gr]);
            c1v[i] = __ldg(&ce[NCANDE + gr]);
        } else { c0v[i] = 0; c1v[i] = 0; }
    }

    float acc[4][4][4];
#pragma unroll
    for (int a = 0; a < 4; a++)
#pragma unroll
        for (int b = 0; b < 4; b++)
#pragma unroll
            for (int c = 0; c < 4; c++) acc[a][b][c] = 0.f;

    for (int k0 = 0; k0 < 256; k0 += 32) {
#pragma unroll
        for (int i = 0; i < 4; i++) {
            int r = rloc[i], cq = cqv[i];
            float4 v = make_float4(0.f, 0.f, 0.f, 0.f);
            if (row0 + r < NCANDE) {
                float4 a = __ldg((const float4*)(P + (size_t)c0v[i] * 512 + k0 + cq));
                float4 b = __ldg((const float4*)(P + (size_t)c1v[i] * 512 + 256 + k0 + cq));
                float4 bb = __ldg((const float4*)(b1 + k0 + cq));
                v.x = fmaxf(a.x + b.x + bb.x, 0.f);
                v.y = fmaxf(a.y + b.y + bb.y, 0.f);
                v.z = fmaxf(a.z + b.z + bb.z, 0.f);
                v.w = fmaxf(a.w + b.w + bb.w, 0.f);
            }
            *(uint4*)(As + r * SA + cq) = cvt4(v);
        }
#pragma unroll
        for (int i = 0; i < 4; i++) {
            int f = tid + i * 256;
            int r = f >> 5, cq = (f & 31) << 2;
            float4 v = __ldg((const float4*)(W2 + (size_t)(k0 + r) * HID + cq));
            *(uint4*)(Bs + r * SB + cq) =
                make_uint4(__float_as_uint(v.x), __float_as_uint(v.y),
                           __float_as_uint(v.z), __float_as_uint(v.w));
        }
        __syncthreads();
#pragma unroll
        for (int ks = 0; ks < 32; ks += 8) {
            unsigned af[4][4], bf[4][2];
#pragma unroll
            for (int mt = 0; mt < 4; mt++) {
                const unsigned* p = As + (warpM + mt * 16 + gid) * SA + ks + tig;
                af[mt][0] = p[0];
                af[mt][1] = p[8 * SA];
                af[mt][2] = p[4];
                af[mt][3] = p[8 * SA + 4];
            }
#pragma unroll
            for (int nt = 0; nt < 4; nt++) {
                const unsigned* p = Bs + (ks + tig) * SB + warpN + nt * 8 + gid;
                bf[nt][0] = p[0];
                bf[nt][1] = p[4 * SB];
            }
#pragma unroll
            for (int mt = 0; mt < 4; mt++)
#pragma unroll
                for (int nt = 0; nt < 4; nt++)
                    mma8(acc[mt][nt], af[mt][0], af[mt][1], af[mt][2], af[mt][3],
                         bf[nt][0], bf[nt][1]);
        }
        __syncthreads();
    }

    // reduce partial scores across the 4 N-warps in smem, then fused sigmoid
    float* sSc = (float*)As;      // 128 floats
    if (tid < 128) sSc[tid] = 0.f;
    __syncthreads();
#pragma unroll
    for (int mt = 0; mt < 4; mt++)
#pragma unroll
        for (int half = 0; half < 2; half++) {
            int r = warpM + mt * 16 + gid + half * 8;
            float p = 0.f;
#pragma unroll
            for (int nt = 0; nt < 4; nt++) {
                int gc = warpN + nt * 8 + tig * 2;
                float vx = fmaxf(acc[mt][nt][half * 2 + 0] + __ldg(&b2[gc]), 0.f);
                float vy = fmaxf(acc[mt][nt][half * 2 + 1] + __ldg(&b2[gc + 1]), 0.f);
                p = fmaf(vx, __ldg(&w3[gc]), p);
                p = fmaf(vy, __ldg(&w3[gc + 1]), p);
            }
            p += __shfl_xor_sync(0xffffffffu, p, 1);
            p += __shfl_xor_sync(0xffffffffu, p, 2);
            if (tig == 0) atomicAdd(&sSc[r], p);
        }
    __syncthreads();
    if (tid < 128) {
        int gr = row0 + tid;
        if (gr < NCANDE) {
            float z = sSc[tid] + __ldg(&b3[0]);
            score[gr] = 1.f / (1.f + expf(-z));
        }
    }
}

// ------------------------------ batch norm apply ------------------------------
__global__ void bn_apply_kernel(const float* __restrict__ Z,
                                const float* __restrict__ stats,
                                const float* __restrict__ gamma,
                                const float* __restrict__ beta,
                                float* __restrict__ out, int ostride) {
    int idx = blockIdx.x * blockDim.x + threadIdx.x;
    if (idx >= N_NODES * HID) return;
    int row = idx / HID, col = idx - row * HID;
    float inv_n = 1.f / (float)N_NODES;
    float mu = stats[col] * inv_n;
    float var = stats[HID + col] * inv_n - mu * mu;
    float scale = rsqrtf(var + BN_EPSF) * gamma[col];
    out[(size_t)row * ostride + col] = rtf((Z[idx] - mu) * scale + beta[col]);
}

// ------------------------------- pooling -------------------------------------
#define POOL_ROWS 1024
__global__ void pool_sum_kernel(const float* __restrict__ emb,
                                const int* __restrict__ batch,
                                float* __restrict__ gsum) {
    int col = blockIdx.y * 128 + threadIdx.x;
    int r0 = blockIdx.x * POOL_ROWS;
    int r1 = min(r0 + POOL_ROWS, N_NODES);
    float acc = 0.f;
    int cur = batch[r0];
    for (int r = r0; r < r1; r++) {
        int b = batch[r];
        if (b != cur) {
            atomicAdd(&gsum[(size_t)cur * EMBW + col], acc);
            acc = 0.f; cur = b;
        }
        acc += emb[(size_t)r * EMBW + col];
    }
    atomicAdd(&gsum[(size_t)cur * EMBW + col], acc);
}

__global__ void count_kernel(const int* __restrict__ batch, float* __restrict__ cnt) {
    __shared__ int hist[N_GRAPH];
    int tid = threadIdx.x;
    if (tid < N_GRAPH) hist[tid] = 0;
    __syncthreads();
    for (int i = blockIdx.x * blockDim.x + tid; i < N_NODES; i += gridDim.x * blockDim.x)
        atomicAdd(&hist[batch[i]], 1);
    __syncthreads();
    if (tid < N_GRAPH && hist[tid]) atomicAdd(&cnt[tid], (float)hist[tid]);
}

__global__ void pool_div_kernel(float* __restrict__ gsum, const float* __restrict__ cnt) {
    int i = blockIdx.x * blockDim.x + threadIdx.x;
    if (i >= N_GRAPH * EMBW) return;
    int g = i / EMBW;
    gsum[i] = gsum[i] / fmaxf(cnt[g], 1.f);
}

// ------------------------- small MLP (classifier) -----------------------------
__global__ void small_mlp_kernel(const float* __restrict__ A,
                                 const float* __restrict__ B,
                                 const float* __restrict__ bias,
                                 float* __restrict__ C,
                                 int M, int N, int K, int relu) {
    int idx = blockIdx.x * blockDim.x + threadIdx.x;
    if (idx >= M * N) return;
    int i = idx / N, j = idx - i * N;
    float s = bias[j];
    const float* a = A + (size_t)i * K;
    for (int k = 0; k < K; k++) s = fmaf(a[k], B[(size_t)k * N + j], s);
    if (relu) s = fmaxf(s, 0.f);
    C[idx] = s;
}

__global__ void logsoftmax_kernel(const float* __restrict__ in, float* __restrict__ out) {
    int g = blockIdx.x;
    int lane = threadIdx.x;
    float v = (lane < NCLS) ? in[g * NCLS + lane] : -INFINITY;
    float m = v;
#pragma unroll
    for (int o = 16; o > 0; o >>= 1) m = fmaxf(m, __shfl_xor_sync(0xffffffffu, m, o));
    float e = (lane < NCLS) ? expf(v - m) : 0.f;
    float s = e;
#pragma unroll
    for (int o = 16; o > 0; o >>= 1) s += __shfl_xor_sync(0xffffffffu, s, o);
    if (lane < NCLS) out[g * NCLS + lane] = v - m - logf(s);
}

// --------------------------------- host --------------------------------------
static void* sym_addr(const void* sym) {
    void* p = nullptr;
    cudaGetSymbolAddress(&p, sym);
    return p;
}

extern "C" void kernel_launch(void* const* d_in, const int* in_sizes, int n_in,
                              void* d_out, int out_size) {
    (void)n_in; (void)out_size;
    const float *x, *cW1, *cb1, *cW2, *cb2, *cgamma, *cbeta, *ceps;
    const float *ncW1, *ncb1, *ncW2, *ncb2, *ncW3, *ncb3, *ncW4, *ncb4;
    const float *epW1, *epb1, *epW2, *epb2, *epW3, *epb3;
    const int *edge_index, *batch, *cand;
    bool dict_order = (in_sizes[1] == 2 * N_EDGES);
    if (dict_order) {
        x          = (const float*)d_in[0];
        edge_index = (const int*)  d_in[1];
        batch      = (const int*)  d_in[2];
        cand       = (const int*)  d_in[3];
        cW1 = (const float*)d_in[4];  cb1 = (const float*)d_in[5];
        cW2 = (const float*)d_in[6];  cb2 = (const float*)d_in[7];
        cgamma = (const float*)d_in[8]; cbeta = (const float*)d_in[9];
        ceps = (const float*)d_in[10];
        ncW1 = (const float*)d_in[11]; ncb1 = (const float*)d_in[12];
        ncW2 = (const float*)d_in[13]; ncb2 = (const float*)d_in[14];
        ncW3 = (const float*)d_in[15]; ncb3 = (const float*)d_in[16];
        ncW4 = (const float*)d_in[17]; ncb4 = (const float*)d_in[18];
        epW1 = (const float*)d_in[19]; epb1 = (const float*)d_in[20];
        epW2 = (const float*)d_in[21]; epb2 = (const float*)d_in[22];
        epW3 = (const float*)d_in[23]; epb3 = (const float*)d_in[24];
    } else {
        x = (const float*)d_in[0];
        cW1 = (const float*)d_in[1];  cb1 = (const float*)d_in[2];
        cW2 = (const float*)d_in[3];  cb2 = (const float*)d_in[4];
        cgamma = (const float*)d_in[5]; cbeta = (const float*)d_in[6];
        ceps = (const float*)d_in[7];
        ncW1 = (const float*)d_in[8];  ncb1 = (const float*)d_in[9];
        ncW2 = (const float*)d_in[10]; ncb2 = (const float*)d_in[11];
        ncW3 = (const float*)d_in[12]; ncb3 = (const float*)d_in[13];
        ncW4 = (const float*)d_in[14]; ncb4 = (const float*)d_in[15];
        epW1 = (const float*)d_in[16]; epb1 = (const float*)d_in[17];
        epW2 = (const float*)d_in[18]; epb2 = (const float*)d_in[19];
        epW3 = (const float*)d_in[20]; epb3 = (const float*)d_in[21];
        edge_index = (const int*)d_in[22];
        batch      = (const int*)d_in[23];
        cand       = (const int*)d_in[24];
    }
    float* out = (float*)d_out;

    float* p_emb  = (float*)sym_addr(g_emb);
    float* p_agg  = (float*)sym_addr(g_agg);
    float* p_z2   = (float*)sym_addr(g_z2);
    float* p_P    = (float*)sym_addr(g_P);
    float* p_st   = (float*)sym_addr(g_stats);
    float* p_gemb = (float*)sym_addr(g_gemb);
    float* p_cnt  = (float*)sym_addr(g_cnt);
    float* p_t1   = (float*)sym_addr(g_t1);
    float* p_t2   = (float*)sym_addr(g_t2);
    float* p_t3   = (float*)sym_addr(g_t3);
    float* p_lg   = (float*)sym_addr(g_logits);
    float* p_wc1  = (float*)sym_addr(g_wc1);
    float* p_wc2  = (float*)sym_addr(g_wc2);
    float* p_w1t  = (float*)sym_addr(g_w1t);
    float* p_w2   = (float*)sym_addr(g_w2);
    int* p_deg  = (int*)sym_addr(g_deg);
    int* p_off  = (int*)sym_addr(g_off);
    int* p_pos  = (int*)sym_addr(g_pos);
    int* p_csr  = (int*)sym_addr(g_csr);
    int* p_bsum = (int*)sym_addr(g_bsum);

    static bool attr_done = false;
    if (!attr_done) {
        cudaFuncSetAttribute(gin_mlp_kernel,
                             cudaFuncAttributeMaxDynamicSharedMemorySize, GIN_SMEM);
        cudaFuncSetAttribute(tf32_gemm_wide,
                             cudaFuncAttributeMaxDynamicSharedMemorySize, WIDE_SMEM);
        attr_done = true;
    }

    const int T = 256;
    const int NODE_BLKS = (N_NODES + 127) / 128;
    const int CAND_BLKS = (NCANDE + 127) / 128;
    const int nScanBlocks = (N_NODES + SCAN_B - 1) / SCAN_B;

    // ============ weight prep ============
    round_weights_kernel<<<(NLAY * HID * HID + T - 1) / T, T>>>(cW1, cW2, epW2,
                                                                p_wc1, p_wc2, p_w2);
    build_w1t_kernel<<<(512 * 512 + T - 1) / T, T>>>(epW1, p_w1t);

    // ================= CSR build =================
    zeroi_kernel<<<(N_NODES + T - 1) / T, T>>>(p_deg, N_NODES);
    hist_kernel<<<(N_EDGES + T - 1) / T, T>>>(edge_index, p_deg);
    scan_block_kernel<<<nScanBlocks, SCAN_B>>>(p_deg, p_off, p_bsum, N_NODES);
    scan_bsum_kernel<<<1, 128>>>(p_bsum, nScanBlocks);
    scan_add_kernel<<<(N_NODES + T) / T, T>>>(p_off, p_bsum, p_pos, N_NODES);
    csr_fill_kernel<<<(N_EDGES + T - 1) / T, T>>>(edge_index, p_pos, p_csr);

    // ================= GIN layers =================
    for (int l = 0; l < NLAY; l++) {
        const float* h = (l == 0) ? x : (p_emb + (l - 1) * HID);
        int hstride = (l == 0) ? HID : EMBW;

        gin_gather_kernel<<<(N_NODES * 32 + T - 1) / T, T>>>(p_off, p_csr, h, hstride,
                                                             ceps, l, p_agg, p_st);
        gin_mlp_kernel<<<NODE_BLKS, 256, GIN_SMEM>>>(
            p_agg,
            p_wc1 + (size_t)l * HID * HID, cb1 + l * HID,
            p_wc2 + (size_t)l * HID * HID, cb2 + l * HID,
            p_z2, p_st);
        bn_apply_kernel<<<(N_NODES * HID + T - 1) / T, T>>>(
            p_z2, p_st, cgamma + l * HID, cbeta + l * HID, p_emb + l * HID, EMBW);
    }

    // ================= global mean pool =================
    zero_kernel<<<(N_GRAPH * EMBW + T - 1) / T, T>>>(p_gemb, N_GRAPH * EMBW);
    zero_kernel<<<1, 64>>>(p_cnt, N_GRAPH);
    {
        dim3 pg((N_NODES + POOL_ROWS - 1) / POOL_ROWS, EMBW / 128);
        pool_sum_kernel<<<pg, 128>>>(p_emb, batch, p_gemb);
    }
    count_kernel<<<128, 256>>>(batch, p_cnt);
    pool_div_kernel<<<(N_GRAPH * EMBW + T - 1) / T, T>>>(p_gemb, p_cnt);

    // ================= node classifier =================
    small_mlp_kernel<<<(N_GRAPH * 256 + T - 1) / T, T>>>(p_gemb, ncW1, ncb1, p_t1,
                                                         N_GRAPH, 256, EMBW, 1);
    small_mlp_kernel<<<(N_GRAPH * 128 + T - 1) / T, T>>>(p_t1, ncW2, ncb2, p_t2,
                                                         N_GRAPH, 128, 256, 1);
    small_mlp_kernel<<<(N_GRAPH * 128 + T - 1) / T, T>>>(p_t2, ncW3, ncb3, p_t3,
                                                         N_GRAPH, 128, 128, 1);
    small_mlp_kernel<<<(N_GRAPH * NCLS + T - 1) / T, T>>>(p_t3, ncW4, ncb4, p_lg,
                                                          N_GRAPH, NCLS, 128, 0);
    logsoftmax_kernel<<<N_GRAPH, 32>>>(p_lg, out);

    // ================= edge predictor =================
    {
        dim3 wg(2, NODE_BLKS);    // N=512 in two 256-wide tiles
        tf32_gemm_wide<<<wg, 256, WIDE_SMEM>>>(p_emb, EMBW, p_w1t, p_P, 512, N_NODES);
    }
    float* scores = out + N_GRAPH * NCLS;
    ep_fused_kernel<<<CAND_BLKS, 256>>>(cand, p_P, epb1, p_w2, epb2, epW3, epb3, scores);
}

// round 16
// speedup vs baseline: 1.1237x; 1.1086x over previous
#include <cuda_runtime.h>
#include <math.h>
#include <stdint.h>

#define N_NODES 100000
#define N_EDGES 1600000
#define N_GRAPH 64
#define HID     128
#define NLAY    4
#define NCLS    16
#define NCANDE  100000
#define EMBW    512           // NLAY*HID
#define BN_EPSF 1e-5f

// ------------------------- persistent device scratch -------------------------
__device__ float g_emb[(size_t)N_NODES * EMBW];
__device__ float g_agg[(size_t)N_NODES * HID];
__device__ float g_z2 [(size_t)N_NODES * HID];
__device__ float g_P  [(size_t)NCANDE * 512];
__device__ float g_stats[2 * HID];
// pre-rounded (tf32-representable) weights
__device__ float g_wc1[NLAY * HID * HID];
__device__ float g_wc2[NLAY * HID * HID];
__device__ float g_w1t[512 * 512];      // combined epW1, transposed [N=512][K=512]
__device__ float g_w2 [256 * 128];
// CSR scratch
__device__ int g_deg[N_NODES];
__device__ int g_off[N_NODES + 1];
__device__ int g_pos[N_NODES];
__device__ int g_csr[N_EDGES];
__device__ int g_bsum[128];

// ------------------------------- small utils --------------------------------
__global__ void zeroi_kernel(int* p, int n) {
    int i = blockIdx.x * blockDim.x + threadIdx.x;
    if (i < n) p[i] = 0;
}

// ----------------------------- tf32 helpers ----------------------------------
__device__ __forceinline__ unsigned f2tf32(float f) {
    unsigned r;
    asm("cvt.rna.tf32.f32 %0, %1;" : "=r"(r) : "f"(f));
    return r;
}
__device__ __forceinline__ float rtf(float f) { return __uint_as_float(f2tf32(f)); }
__device__ __forceinline__ uint4 cvt4(float4 v) {
    uint4 w;
    w.x = f2tf32(v.x); w.y = f2tf32(v.y); w.z = f2tf32(v.z); w.w = f2tf32(v.w);
    return w;
}
__device__ __forceinline__ void mma8(float* d, unsigned a0, unsigned a1, unsigned a2,
                                     unsigned a3, unsigned b0, unsigned b1) {
    asm volatile(
        "mma.sync.aligned.m16n8k8.row.col.f32.tf32.tf32.f32 "
        "{%0,%1,%2,%3}, {%4,%5,%6,%7}, {%8,%9}, {%0,%1,%2,%3};"
        : "+f"(d[0]), "+f"(d[1]), "+f"(d[2]), "+f"(d[3])
        : "r"(a0), "r"(a1), "r"(a2), "r"(a3), "r"(b0), "r"(b1));
}
__device__ __forceinline__ void cp16(unsigned sdst, const void* gsrc, int srcbytes) {
    asm volatile("cp.async.ca.shared.global [%0], [%1], 16, %2;"
                 :: "r"(sdst), "l"(gsrc), "r"(srcbytes));
}
#define CP_COMMIT() asm volatile("cp.async.commit_group;")
#define CP_WAIT0()  asm volatile("cp.async.wait_group 0;" ::: "memory")

// ldmatrix: reg i = matrix i; lane l gets word (row l>>2, chunk l&3) of each.
__device__ __forceinline__ void ldsm4(unsigned& r0, unsigned& r1, unsigned& r2,
                                      unsigned& r3, uint32_t addr) {
    asm volatile("ldmatrix.sync.aligned.m8n8.x4.shared.b16 {%0,%1,%2,%3}, [%4];"
                 : "=r"(r0), "=r"(r1), "=r"(r2), "=r"(r3) : "r"(addr));
}

// round weights once (makes HW tf32 truncation exact == cvt.rna semantics)
__global__ void round_weights_kernel(const float* __restrict__ cW1,
                                     const float* __restrict__ cW2,
                                     const float* __restrict__ epW2,
                                     float* __restrict__ wc1, float* __restrict__ wc2,
                                     float* __restrict__ w2) {
    int i = blockIdx.x * blockDim.x + threadIdx.x;
    if (i < NLAY * HID * HID) { wc1[i] = rtf(cW1[i]); wc2[i] = rtf(cW2[i]); }
    if (i < 256 * 128)  w2[i] = rtf(epW2[i]);
}

// build combined transposed [N=512][K=512] epW1 (halves side by side in N)
__global__ void build_w1t_kernel(const float* __restrict__ epW1, float* __restrict__ w1t) {
    int i = blockIdx.x * blockDim.x + threadIdx.x;   // i = n*512 + k
    if (i >= 512 * 512) return;
    int n = i >> 9, k = i & 511;
    float v = (n < 256) ? epW1[(size_t)k * 256 + n]
                        : epW1[(size_t)(512 + k) * 256 + (n - 256)];
    w1t[i] = rtf(v);
}

// ------------------------------ CSR build ------------------------------------
__global__ void hist_kernel(const int* __restrict__ ei, int* __restrict__ deg) {
    int e = blockIdx.x * blockDim.x + threadIdx.x;
    if (e < N_EDGES) atomicAdd(&deg[ei[N_EDGES + e]], 1);
}

#define SCAN_B 1024
__global__ void scan_block_kernel(const int* __restrict__ deg, int* __restrict__ off,
                                  int* __restrict__ bsum, int n) {
    __shared__ int sh[SCAN_B];
    int g = blockIdx.x * SCAN_B + threadIdx.x;
    int v = (g < n) ? deg[g] : 0;
    sh[threadIdx.x] = v;
    __syncthreads();
#pragma unroll
    for (int o = 1; o < SCAN_B; o <<= 1) {
        int t = (threadIdx.x >= o) ? sh[threadIdx.x - o] : 0;
        __syncthreads();
        sh[threadIdx.x] += t;
        __syncthreads();
    }
    if (g < n) off[g] = sh[threadIdx.x] - v;
    if (threadIdx.x == SCAN_B - 1) bsum[blockIdx.x] = sh[SCAN_B - 1];
}

__global__ void scan_bsum_kernel(int* __restrict__ bsum, int nb) {
    __shared__ int sh[128];
    int v = (threadIdx.x < nb) ? bsum[threadIdx.x] : 0;
    sh[threadIdx.x] = v;
    __syncthreads();
#pragma unroll
    for (int o = 1; o < 128; o <<= 1) {
        int t = (threadIdx.x >= o) ? sh[threadIdx.x - o] : 0;
        __syncthreads();
        sh[threadIdx.x] += t;
        __syncthreads();
    }
    if (threadIdx.x < nb) bsum[threadIdx.x] = sh[threadIdx.x] - v;
}

__global__ void scan_add_kernel(int* __restrict__ off, const int* __restrict__ bsum,
                                int* __restrict__ pos, int n) {
    int g = blockIdx.x * blockDim.x + threadIdx.x;
    if (g < n) {
        int o = off[g] + bsum[g / SCAN_B];
        off[g] = o;
        pos[g] = o;
    }
    if (g == n) off[n] = N_EDGES;
}

__global__ void csr_fill_kernel(const int* __restrict__ ei, int* __restrict__ pos,
                                int* __restrict__ csr) {
    int e = blockIdx.x * blockDim.x + threadIdx.x;
    if (e >= N_EDGES) return;
    int dst = ei[N_EDGES + e];
    int p = atomicAdd(&pos[dst], 1);
    csr[p] = ei[e];
}

// --------- GIN aggregation: warp-per-node gather (+ zero stats by block 0) ----
__global__ void gin_gather_kernel(const int* __restrict__ off,
                                  const int* __restrict__ csr,
                                  const float* __restrict__ h, int hstride,
                                  const float* __restrict__ ceps, int layer,
                                  float* __restrict__ agg,
                                  float* __restrict__ stats) {
    if (blockIdx.x == 0 && threadIdx.x < 2 * HID) stats[threadIdx.x] = 0.f;
    int node = (blockIdx.x * blockDim.x + threadIdx.x) >> 5;
    int lane = threadIdx.x & 31;
    if (node >= N_NODES) return;
    int s = off[node], e = off[node + 1];
    float c = 1.f + __ldg(&ceps[layer]);
    float4 acc = __ldg((const float4*)(h + (size_t)node * hstride) + lane);
    acc.x *= c; acc.y *= c; acc.z *= c; acc.w *= c;
    for (int i = s; i < e; i++) {
        int src = __ldg(&csr[i]);
        float4 v = __ldg((const float4*)(h + (size_t)src * hstride) + lane);
        acc.x += v.x; acc.y += v.y; acc.z += v.z; acc.w += v.w;
    }
    acc.x = rtf(acc.x); acc.y = rtf(acc.y); acc.z = rtf(acc.z); acc.w = rtf(acc.w);
    *((float4*)(agg + (size_t)node * HID) + lane) = acc;
}

#define SA  36
#define SZ  132
#define SW  136
#define SB  136
#define SBT 36
#define GIN_SMEM ((128 * SZ + 32 * SW) * 4)                 // 84992 B -> 2 CTA/SM
#define WIDE_SMEM ((2 * 128 * SA + 2 * 256 * SBT) * 4)      // 110592 B

// ---- GEMM phase: A persistent in smem (128xSZ), weight chunks reg-prefetched --
__device__ __forceinline__ void gemm128(const unsigned* __restrict__ z1s,
                                        unsigned* __restrict__ Ws,
                                        const float* __restrict__ W,
                                        float acc[4][4][4],
                                        int tid, int warpM, int warpN,
                                        int gid, int tig) {
#pragma unroll
    for (int a = 0; a < 4; a++)
#pragma unroll
        for (int b = 0; b < 4; b++)
#pragma unroll
            for (int c = 0; c < 4; c++) acc[a][b][c] = 0.f;

    int wr = tid >> 5, wcq = (tid & 31) << 2;
    float4 pre[4];
#pragma unroll
    for (int i = 0; i < 4; i++)
        pre[i] = __ldg((const float4*)(W + (size_t)(wr + i * 8) * HID + wcq));

    for (int k0 = 0; k0 < 128; k0 += 32) {
#pragma unroll
        for (int i = 0; i < 4; i++)
            *(uint4*)(Ws + (wr + i * 8) * SW + wcq) = cvt4(pre[i]);
        __syncthreads();
        if (k0 < 96) {
#pragma unroll
            for (int i = 0; i < 4; i++)
                pre[i] = __ldg((const float4*)(W + (size_t)(k0 + 32 + wr + i * 8) * HID + wcq));
        }
#pragma unroll
        for (int ks = 0; ks < 32; ks += 8) {
            unsigned af[4][4], bf[4][2];
#pragma unroll
            for (int mt = 0; mt < 4; mt++) {
                const unsigned* p = z1s + (warpM + mt * 16 + gid) * SZ + k0 + ks + tig;
                af[mt][0] = p[0];
                af[mt][1] = p[8 * SZ];
                af[mt][2] = p[4];
                af[mt][3] = p[8 * SZ + 4];
            }
#pragma unroll
            for (int nt = 0; nt < 4; nt++) {
                const unsigned* p = Ws + (ks + tig) * SW + warpN + nt * 8 + gid;
                bf[nt][0] = p[0];
                bf[nt][1] = p[4 * SW];
            }
#pragma unroll
            for (int mt = 0; mt < 4; mt++)
#pragma unroll
                for (int nt = 0; nt < 4; nt++)
                    mma8(acc[mt][nt], af[mt][0], af[mt][1], af[mt][2], af[mt][3],
                         bf[nt][0], bf[nt][1]);
        }
        __syncthreads();
    }
}

// ---- fused node-layer MLP: z2 = relu(relu(agg@W1+b1)@W2+b2), + BN stats ----
__global__ __launch_bounds__(256, 2)
void gin_mlp_kernel(const float* __restrict__ agg,
                    const float* __restrict__ W1, const float* __restrict__ b1,
                    const float* __restrict__ W2, const float* __restrict__ b2,
                    float* __restrict__ z2out, float* __restrict__ stats) {
    extern __shared__ unsigned dsm[];
    unsigned* z1s = dsm;
    unsigned* Ws  = dsm + 128 * SZ;
    int tid = threadIdx.x;
    int warp = tid >> 5, lane = tid & 31;
    int gid = lane >> 2, tig = lane & 3;
    int row0 = blockIdx.x * 128;
    int warpM = (warp >> 2) * 64;
    int warpN = (warp & 3) * 32;

    {
        unsigned sZ = (unsigned)__cvta_generic_to_shared(z1s);
        int r = tid >> 1, cb = (tid & 1) * 64;
        int gr = row0 + r;
        int ok = (gr < N_NODES) ? 16 : 0;
        const float* src = agg + (size_t)(ok ? gr : 0) * HID + cb;
#pragma unroll
        for (int c = 0; c < 16; c++)
            cp16(sZ + (unsigned)(r * SZ + cb + c * 4) * 4u, src + c * 4, ok);
        CP_COMMIT();
        CP_WAIT0();
    }
    __syncthreads();

    float acc[4][4][4];

    gemm128(z1s, Ws, W1, acc, tid, warpM, warpN, gid, tig);
#pragma unroll
    for (int mt = 0; mt < 4; mt++)
#pragma unroll
        for (int half = 0; half < 2; half++) {
            int r = warpM + mt * 16 + gid + half * 8;
#pragma unroll
            for (int nt = 0; nt < 4; nt++) {
                int gc = warpN + nt * 8 + tig * 2;
                float vx = fmaxf(acc[mt][nt][half * 2 + 0] + __ldg(&b1[gc]), 0.f);
                float vy = fmaxf(acc[mt][nt][half * 2 + 1] + __ldg(&b1[gc + 1]), 0.f);
                z1s[r * SZ + gc]     = f2tf32(vx);
                z1s[r * SZ + gc + 1] = f2tf32(vy);
            }
        }
    __syncthreads();

    gemm128(z1s, Ws, W2, acc, tid, warpM, warpN, gid, tig);

    float* sS = (float*)Ws;
    float* sQ = sS + 128;
    if (tid < 256) ((float*)Ws)[tid] = 0.f;
    __syncthreads();

    float sumS[4][2] = {}, sumQ[4][2] = {};
#pragma unroll
    for (int mt = 0; mt < 4; mt++)
#pragma unroll
        for (int half = 0; half < 2; half++) {
            int gr = row0 + warpM + mt * 16 + gid + half * 8;
            if (gr >= N_NODES) continue;
#pragma unroll
            for (int nt = 0; nt < 4; nt++) {
                int gc = warpN + nt * 8 + tig * 2;
                float vx = fmaxf(acc[mt][nt][half * 2 + 0] + __ldg(&b2[gc]), 0.f);
                float vy = fmaxf(acc[mt][nt][half * 2 + 1] + __ldg(&b2[gc + 1]), 0.f);
                *(float2*)(z2out + (size_t)gr * HID + gc) = make_float2(vx, vy);
                sumS[nt][0] += vx; sumQ[nt][0] += vx * vx;
                sumS[nt][1] += vy; sumQ[nt][1] += vy * vy;
            }
        }
#pragma unroll
    for (int nt = 0; nt < 4; nt++) {
        int gc = warpN + nt * 8 + tig * 2;
        atomicAdd(&sS[gc],     sumS[nt][0]);
        atomicAdd(&sS[gc + 1], sumS[nt][1]);
        atomicAdd(&sQ[gc],     sumQ[nt][0]);
        atomicAdd(&sQ[gc + 1], sumQ[nt][1]);
    }
    __syncthreads();
    if (tid < 128) {
        atomicAdd(&stats[tid],       sS[tid]);
        atomicAdd(&stats[HID + tid], sQ[tid]);
    }
}

// ------- WIDE P-GEMM with ldmatrix (coalesced staging): 128x256, K=512 -------
__global__ __launch_bounds__(256, 1)
void tf32_gemm_wide(const float* __restrict__ A, int lda,
                    const float* __restrict__ Bt,
                    float* __restrict__ C, int ldc, int M) {
    extern __shared__ float sm[];
    float* Ab[2] = { sm, sm + 128 * SA };
    float* Bb[2] = { sm + 2 * 128 * SA, sm + 2 * 128 * SA + 256 * SBT };
    int tid = threadIdx.x;
    int warp = tid >> 5, lane = tid & 31;
    int row0 = blockIdx.y * 128;
    int col0 = blockIdx.x * 256;
    int warpM = (warp >> 2) * 64;
    int warpN = (warp & 3) * 64;

    int ar = tid >> 3, acq = (tid & 7) << 2;

    int a_row = lane & 15, a_koff = (lane >> 4) * 4;
    int b_row = lane & 7, b_koff = ((lane >> 3) & 1) * 4;
    int b_nsel = (lane >> 4);

    float acc[4][8][4];
#pragma unroll
    for (int a = 0; a < 4; a++)
#pragma unroll
        for (int b = 0; b < 8; b++)
#pragma unroll
            for (int c = 0; c < 4; c++) acc[a][b][c] = 0.f;

    {
        unsigned sA = (unsigned)__cvta_generic_to_shared(Ab[0]);
        unsigned sB = (unsigned)__cvta_generic_to_shared(Bb[0]);
#pragma unroll
        for (int i = 0; i < 4; i++) {
            int r = ar + i * 32;
            int gr = row0 + r;
            int ok = (gr < M) ? 16 : 0;
            cp16(sA + (unsigned)(r * SA + acq) * 4u,
                 A + (size_t)(ok ? gr : 0) * lda + acq, ok);
        }
#pragma unroll
        for (int i = 0; i < 8; i++) {
            int f = tid + i * 256;
            int r = f >> 3, c = (f & 7) << 2;
            cp16(sB + (unsigned)(r * SBT + c) * 4u,
                 Bt + (size_t)(col0 + r) * 512 + c, 16);
        }
        CP_COMMIT();
    }

    for (int t = 0; t < 16; t++) {
        CP_WAIT0();
        __syncthreads();
        if (t + 1 < 16) {
            int nb = (t + 1) & 1;
            int k0 = (t + 1) << 5;
            unsigned sA = (unsigned)__cvta_generic_to_shared(Ab[nb]);
            unsigned sB = (unsigned)__cvta_generic_to_shared(Bb[nb]);
#pragma unroll
            for (int i = 0; i < 4; i++) {
                int r = ar + i * 32;
                int gr = row0 + r;
                int ok = (gr < M) ? 16 : 0;
                cp16(sA + (unsigned)(r * SA + acq) * 4u,
                     A + (size_t)(ok ? gr : 0) * lda + k0 + acq, ok);
            }
#pragma unroll
            for (int i = 0; i < 8; i++) {
                int f = tid + i * 256;
                int r = f >> 3, c = (f & 7) << 2;
                cp16(sB + (unsigned)(r * SBT + c) * 4u,
                     Bt + (size_t)(col0 + r) * 512 + k0 + c, 16);
            }
            CP_COMMIT();
        }
        unsigned aBase = (unsigned)__cvta_generic_to_shared(Ab[t & 1]);
        unsigned bBase = (unsigned)__cvta_generic_to_shared(Bb[t & 1]);
#pragma unroll
        for (int ks = 0; ks < 32; ks += 8) {
            unsigned af[4][4], bf[8][2];
#pragma unroll
            for (int mt = 0; mt < 4; mt++) {
                uint32_t addr = aBase +
                    (unsigned)((warpM + mt * 16 + a_row) * SA + ks + a_koff) * 4u;
                ldsm4(af[mt][0], af[mt][1], af[mt][2], af[mt][3], addr);
            }
#pragma unroll
            for (int j = 0; j < 4; j++) {
                uint32_t addr = bBase +
                    (unsigned)((warpN + (2 * j + b_nsel) * 8 + b_row) * SBT
                               + ks + b_koff) * 4u;
                ldsm4(bf[2 * j][0], bf[2 * j][1], bf[2 * j + 1][0], bf[2 * j + 1][1],
                      addr);
            }
#pragma unroll
            for (int mt = 0; mt < 4; mt++)
#pragma unroll
                for (int nt = 0; nt < 8; nt++)
                    mma8(acc[mt][nt], af[mt][0], af[mt][1], af[mt][2], af[mt][3],
                         bf[nt][0], bf[nt][1]);
        }
    }

    int gid = lane >> 2, tig = lane & 3;
#pragma unroll
    for (int mt = 0; mt < 4; mt++) {
#pragma unroll
        for (int half = 0; half < 2; half++) {
            int gr = row0 + warpM + mt * 16 + gid + half * 8;
            if (gr >= M) continue;
#pragma unroll
            for (int nt = 0; nt < 8; nt++) {
                int gc = col0 + warpN + nt * 8 + tig * 2;
                float2 v;
                v.x = acc[mt][nt][half * 2 + 0];
                v.y = acc[mt][nt][half * 2 + 1];
                *(float2*)(C + (size_t)gr * ldc + gc) = v;
            }
        }
    }
}

// -- fused edge kernel: gather + GEMM(K=256) + score dot + smem reduce+sigmoid --
__global__ __launch_bounds__(256, 2)
void ep_fused_kernel(const int* __restrict__ ce,
                     const float* __restrict__ P,
                     const float* __restrict__ b1,
                     const float* __restrict__ W2,
                     const float* __restrict__ b2,
                     const float* __restrict__ w3,
                     const float* __restrict__ b3,
                     float* __restrict__ score) {
    __shared__ unsigned As[128 * SA];
    __shared__ unsigned Bs[32 * SB];
    int tid = threadIdx.x;
    int warp = tid >> 5, lane = tid & 31;
    int gid = lane >> 2, tig = lane & 3;
    int row0 = blockIdx.x * 128;
    int warpM = (warp >> 2) * 64;
    int warpN = (warp & 3) * 32;

    int rloc[4], c0v[4], c1v[4], cqv[4];
#pragma unroll
    for (int i = 0; i < 4; i++) {
        int f = tid + i * 256;
        rloc[i] = f >> 3;
        cqv[i] = (f & 7) << 2;
        int gr = row0 + rloc[i];
        if (gr < NCANDE) {
            c0v[i] = __ldg(&ce[gr]);
            c1v[i] = __ldg(&ce[NCANDE + gr]);
        } else { c0v[i] = 0; c1v[i] = 0; }
    }

    float acc[4][4][4];
#pragma unroll
    for (int a = 0; a < 4; a++)
#pragma unroll
        for (int b = 0; b < 4; b++)
#pragma unroll
            for (int c = 0; c < 4; c++) acc[a][b][c] = 0.f;

    for (int k0 = 0; k0 < 256; k0 += 32) {
#pragma unroll
        for (int i = 0; i < 4; i++) {
            int r = rloc[i], cq = cqv[i];
            float4 v = make_float4(0.f, 0.f, 0.f, 0.f);
            if (row0 + r < NCANDE) {
                float4 a = __ldg((const float4*)(P + (size_t)c0v[i] * 512 + k0 + cq));
                float4 b = __ldg((const float4*)(P + (size_t)c1v[i] * 512 + 256 + k0 + cq));
                float4 bb = __ldg((const float4*)(b1 + k0 + cq));
                v.x = fmaxf(a.x + b.x + bb.x, 0.f);
                v.y = fmaxf(a.y + b.y + bb.y, 0.f);
                v.z = fmaxf(a.z + b.z + bb.z, 0.f);
                v.w = fmaxf(a.w + b.w + bb.w, 0.f);
            }
            *(uint4*)(As + r * SA + cq) = cvt4(v);
        }
#pragma unroll
        for (int i = 0; i < 4; i++) {
            int f = tid + i * 256;
            int r = f >> 5, cq = (f & 31) << 2;
            float4 v = __ldg((const float4*)(W2 + (size_t)(k0 + r) * HID + cq));
            *(uint4*)(Bs + r * SB + cq) =
                make_uint4(__float_as_uint(v.x), __float_as_uint(v.y),
                           __float_as_uint(v.z), __float_as_uint(v.w));
        }
        __syncthreads();
#pragma unroll
        for (int ks = 0; ks < 32; ks += 8) {
            unsigned af[4][4], bf[4][2];
#pragma unroll
            for (int mt = 0; mt < 4; mt++) {
                const unsigned* p = As + (warpM + mt * 16 + gid) * SA + ks + tig;
                af[mt][0] = p[0];
                af[mt][1] = p[8 * SA];
                af[mt][2] = p[4];
                af[mt][3] = p[8 * SA + 4];
            }
#pragma unroll
            for (int nt = 0; nt < 4; nt++) {
                const unsigned* p = Bs + (ks + tig) * SB + warpN + nt * 8 + gid;
                bf[nt][0] = p[0];
                bf[nt][1] = p[4 * SB];
            }
#pragma unroll
            for (int mt = 0; mt < 4; mt++)
#pragma unroll
                for (int nt = 0; nt < 4; nt++)
                    mma8(acc[mt][nt], af[mt][0], af[mt][1], af[mt][2], af[mt][3],
                         bf[nt][0], bf[nt][1]);
        }
        __syncthreads();
    }

    float* sSc = (float*)As;
    if (tid < 128) sSc[tid] = 0.f;
    __syncthreads();
#pragma unroll
    for (int mt = 0; mt < 4; mt++)
#pragma unroll
        for (int half = 0; half < 2; half++) {
            int r = warpM + mt * 16 + gid + half * 8;
            float p = 0.f;
#pragma unroll
            for (int nt = 0; nt < 4; nt++) {
                int gc = warpN + nt * 8 + tig * 2;
                float vx = fmaxf(acc[mt][nt][half * 2 + 0] + __ldg(&b2[gc]), 0.f);
                float vy = fmaxf(acc[mt][nt][half * 2 + 1] + __ldg(&b2[gc + 1]), 0.f);
                p = fmaf(vx, __ldg(&w3[gc]), p);
                p = fmaf(vy, __ldg(&w3[gc + 1]), p);
            }
            p += __shfl_xor_sync(0xffffffffu, p, 1);
            p += __shfl_xor_sync(0xffffffffu, p, 2);
            if (tig == 0) atomicAdd(&sSc[r], p);
        }
    __syncthreads();
    if (tid < 128) {
        int gr = row0 + tid;
        if (gr < NCANDE) {
            float z = sSc[tid] + __ldg(&b3[0]);
            score[gr] = 1.f / (1.f + expf(-z));
        }
    }
}

// ------------------------------ batch norm apply ------------------------------
__global__ void bn_apply_kernel(const float* __restrict__ Z,
                                const float* __restrict__ stats,
                                const float* __restrict__ gamma,
                                const float* __restrict__ beta,
                                float* __restrict__ out, int ostride) {
    int idx = blockIdx.x * blockDim.x + threadIdx.x;
    if (idx >= N_NODES * HID) return;
    int row = idx / HID, col = idx - row * HID;
    float inv_n = 1.f / (float)N_NODES;
    float mu = stats[col] * inv_n;
    float var = stats[HID + col] * inv_n - mu * mu;
    float scale = rsqrtf(var + BN_EPSF) * gamma[col];
    out[(size_t)row * ostride + col] = rtf((Z[idx] - mu) * scale + beta[col]);
}

// ------ fused classifier: per-graph mean pool + 4-layer MLP + log-softmax -----
// grid = N_GRAPH blocks, 256 threads. batch sorted -> graph rows contiguous.
__global__ __launch_bounds__(256, 4)
void classifier_kernel(const float* __restrict__ emb,
                       const int* __restrict__ batch,
                       const float* __restrict__ W1, const float* __restrict__ b1,
                       const float* __restrict__ W2, const float* __restrict__ b2,
                       const float* __restrict__ W3, const float* __restrict__ b3,
                       const float* __restrict__ W4, const float* __restrict__ b4,
                       float* __restrict__ out) {
    __shared__ float sg[EMBW];      // pooled graph embedding
    __shared__ float st1[256];
    __shared__ float st2[128];
    __shared__ float st3[128];
    __shared__ float slg[NCLS];
    int g = blockIdx.x;
    int tid = threadIdx.x;

    // lower_bound(batch, g) and lower_bound(batch, g+1)
    int lo = 0, hi = N_NODES;
    while (lo < hi) { int m = (lo + hi) >> 1; if (batch[m] < g) lo = m + 1; else hi = m; }
    int s0 = lo;
    lo = s0; hi = N_NODES;
    while (lo < hi) { int m = (lo + hi) >> 1; if (batch[m] < g + 1) lo = m + 1; else hi = m; }
    int s1 = lo;

    float inv = 1.f / fmaxf((float)(s1 - s0), 1.f);
    float a0 = 0.f, a1 = 0.f;
    for (int r = s0; r < s1; r++) {
        a0 += __ldg(emb + (size_t)r * EMBW + tid);
        a1 += __ldg(emb + (size_t)r * EMBW + tid + 256);
    }
    sg[tid]       = a0 * inv;
    sg[tid + 256] = a1 * inv;
    __syncthreads();

    // t1 = relu(gemb @ W1 + b1)   [512 -> 256]
    {
        float v = __ldg(&b1[tid]);
        for (int k = 0; k < EMBW; k++) v = fmaf(sg[k], __ldg(&W1[(size_t)k * 256 + tid]), v);
        st1[tid] = fmaxf(v, 0.f);
    }
    __syncthreads();
    // t2 = relu(t1 @ W2 + b2)     [256 -> 128]
    if (tid < 128) {
        float v = __ldg(&b2[tid]);
        for (int k = 0; k < 256; k++) v = fmaf(st1[k], __ldg(&W2[(size_t)k * 128 + tid]), v);
        st2[tid] = fmaxf(v, 0.f);
    }
    __syncthreads();
    // t3 = relu(t2 @ W3 + b3)     [128 -> 128]
    if (tid < 128) {
        float v = __ldg(&b3[tid]);
        for (int k = 0; k < 128; k++) v = fmaf(st2[k], __ldg(&W3[(size_t)k * 128 + tid]), v);
        st3[tid] = fmaxf(v, 0.f);
    }
    __syncthreads();
    // logits = t3 @ W4 + b4       [128 -> 16]
    if (tid < NCLS) {
        float v = __ldg(&b4[tid]);
        for (int k = 0; k < 128; k++) v = fmaf(st3[k], __ldg(&W4[(size_t)k * NCLS + tid]), v);
        slg[tid] = v;
    }
    __syncthreads();
    // log-softmax by warp 0
    if (tid < 32) {
        float v = (tid < NCLS) ? slg[tid] : -INFINITY;
        float m = v;
#pragma unroll
        for (int o = 16; o > 0; o >>= 1) m = fmaxf(m, __shfl_xor_sync(0xffffffffu, m, o));
        float e = (tid < NCLS) ? expf(v - m) : 0.f;
        float s = e;
#pragma unroll
        for (int o = 16; o > 0; o >>= 1) s += __shfl_xor_sync(0xffffffffu, s, o);
        if (tid < NCLS) out[g * NCLS + tid] = v - m - logf(s);
    }
}

// --------------------------------- host --------------------------------------
static void* sym_addr(const void* sym) {
    void* p = nullptr;
    cudaGetSymbolAddress(&p, sym);
    return p;
}

extern "C" void kernel_launch(void* const* d_in, const int* in_sizes, int n_in,
                              void* d_out, int out_size) {
    (void)n_in; (void)out_size;
    const float *x, *cW1, *cb1, *cW2, *cb2, *cgamma, *cbeta, *ceps;
    const float *ncW1, *ncb1, *ncW2, *ncb2, *ncW3, *ncb3, *ncW4, *ncb4;
    const float *epW1, *epb1, *epW2, *epb2, *epW3, *epb3;
    const int *edge_index, *batch, *cand;
    bool dict_order = (in_sizes[1] == 2 * N_EDGES);
    if (dict_order) {
        x          = (const float*)d_in[0];
        edge_index = (const int*)  d_in[1];
        batch      = (const int*)  d_in[2];
        cand       = (const int*)  d_in[3];
        cW1 = (const float*)d_in[4];  cb1 = (const float*)d_in[5];
        cW2 = (const float*)d_in[6];  cb2 = (const float*)d_in[7];
        cgamma = (const float*)d_in[8]; cbeta = (const float*)d_in[9];
        ceps = (const float*)d_in[10];
        ncW1 = (const float*)d_in[11]; ncb1 = (const float*)d_in[12];
        ncW2 = (const float*)d_in[13]; ncb2 = (const float*)d_in[14];
        ncW3 = (const float*)d_in[15]; ncb3 = (const float*)d_in[16];
        ncW4 = (const float*)d_in[17]; ncb4 = (const float*)d_in[18];
        epW1 = (const float*)d_in[19]; epb1 = (const float*)d_in[20];
        epW2 = (const float*)d_in[21]; epb2 = (const float*)d_in[22];
        epW3 = (const float*)d_in[23]; epb3 = (const float*)d_in[24];
    } else {
        x = (const float*)d_in[0];
        cW1 = (const float*)d_in[1];  cb1 = (const float*)d_in[2];
        cW2 = (const float*)d_in[3];  cb2 = (const float*)d_in[4];
        cgamma = (const float*)d_in[5]; cbeta = (const float*)d_in[6];
        ceps = (const float*)d_in[7];
        ncW1 = (const float*)d_in[8];  ncb1 = (const float*)d_in[9];
        ncW2 = (const float*)d_in[10]; ncb2 = (const float*)d_in[11];
        ncW3 = (const float*)d_in[12]; ncb3 = (const float*)d_in[13];
        ncW4 = (const float*)d_in[14]; ncb4 = (const float*)d_in[15];
        epW1 = (const float*)d_in[16]; epb1 = (const float*)d_in[17];
        epW2 = (const float*)d_in[18]; epb2 = (const float*)d_in[19];
        epW3 = (const float*)d_in[20]; epb3 = (const float*)d_in[21];
        edge_index = (const int*)d_in[22];
        batch      = (const int*)d_in[23];
        cand       = (const int*)d_in[24];
    }
    float* out = (float*)d_out;

    float* p_emb  = (float*)sym_addr(g_emb);
    float* p_agg  = (float*)sym_addr(g_agg);
    float* p_z2   = (float*)sym_addr(g_z2);
    float* p_P    = (float*)sym_addr(g_P);
    float* p_st   = (float*)sym_addr(g_stats);
    float* p_wc1  = (float*)sym_addr(g_wc1);
    float* p_wc2  = (float*)sym_addr(g_wc2);
    float* p_w1t  = (float*)sym_addr(g_w1t);
    float* p_w2   = (float*)sym_addr(g_w2);
    int* p_deg  = (int*)sym_addr(g_deg);
    int* p_off  = (int*)sym_addr(g_off);
    int* p_pos  = (int*)sym_addr(g_pos);
    int* p_csr  = (int*)sym_addr(g_csr);
    int* p_bsum = (int*)sym_addr(g_bsum);

    static bool attr_done = false;
    if (!attr_done) {
        cudaFuncSetAttribute(gin_mlp_kernel,
                             cudaFuncAttributeMaxDynamicSharedMemorySize, GIN_SMEM);
        cudaFuncSetAttribute(tf32_gemm_wide,
                             cudaFuncAttributeMaxDynamicSharedMemorySize, WIDE_SMEM);
        attr_done = true;
    }

    const int T = 256;
    const int NODE_BLKS = (N_NODES + 127) / 128;
    const int CAND_BLKS = (NCANDE + 127) / 128;
    const int nScanBlocks = (N_NODES + SCAN_B - 1) / SCAN_B;

    // ============ weight prep ============
    round_weights_kernel<<<(NLAY * HID * HID + T - 1) / T, T>>>(cW1, cW2, epW2,
                                                                p_wc1, p_wc2, p_w2);
    build_w1t_kernel<<<(512 * 512 + T - 1) / T, T>>>(epW1, p_w1t);

    // ================= CSR build =================
    zeroi_kernel<<<(N_NODES + T - 1) / T, T>>>(p_deg, N_NODES);
    hist_kernel<<<(N_EDGES + T - 1) / T, T>>>(edge_index, p_deg);
    scan_block_kernel<<<nScanBlocks, SCAN_B>>>(p_deg, p_off, p_bsum, N_NODES);
    scan_bsum_kernel<<<1, 128>>>(p_bsum, nScanBlocks);
    scan_add_kernel<<<(N_NODES + T) / T, T>>>(p_off, p_bsum, p_pos, N_NODES);
    csr_fill_kernel<<<(N_EDGES + T - 1) / T, T>>>(edge_index, p_pos, p_csr);

    // ================= GIN layers =================
    for (int l = 0; l < NLAY; l++) {
        const float* h = (l == 0) ? x : (p_emb + (l - 1) * HID);
        int hstride = (l == 0) ? HID : EMBW;

        gin_gather_kernel<<<(N_NODES * 32 + T - 1) / T, T>>>(p_off, p_csr, h, hstride,
                                                             ceps, l, p_agg, p_st);
        gin_mlp_kernel<<<NODE_BLKS, 256, GIN_SMEM>>>(
            p_agg,
            p_wc1 + (size_t)l * HID * HID, cb1 + l * HID,
            p_wc2 + (size_t)l * HID * HID, cb2 + l * HID,
            p_z2, p_st);
        bn_apply_kernel<<<(N_NODES * HID + T - 1) / T, T>>>(
            p_z2, p_st, cgamma + l * HID, cbeta + l * HID, p_emb + l * HID, EMBW);
    }

    // ================= node classifier (fully fused) =================
    classifier_kernel<<<N_GRAPH, 256>>>(p_emb, batch,
                                        ncW1, ncb1, ncW2, ncb2,
                                        ncW3, ncb3, ncW4, ncb4, out);

    // ================= edge predictor =================
    {
        dim3 wg(2, NODE_BLKS);    // N=512 in two 256-wide tiles
        tf32_gemm_wide<<<wg, 256, WIDE_SMEM>>>(p_emb, EMBW, p_w1t, p_P, 512, N_NODES);
    }
    float* scores = out + N_GRAPH * NCLS;
    ep_fused_kernel<<<CAND_BLKS, 256>>>(cand, p_P, epb1, p_w2, epb2, epW3, epb3, scores);
}

// round 17
// speedup vs baseline: 1.1724x; 1.0433x over previous
#include <cuda_runtime.h>
#include <math.h>
#include <stdint.h>

#define N_NODES 100000
#define N_EDGES 1600000
#define N_GRAPH 64
#define HID     128
#define NLAY    4
#define NCLS    16
#define NCANDE  100000
#define EMBW    512           // NLAY*HID
#define BN_EPSF 1e-5f

// ------------------------- persistent device scratch -------------------------
__device__ float g_emb[(size_t)N_NODES * EMBW];
__device__ float g_agg[(size_t)N_NODES * HID];
__device__ float g_z2 [(size_t)N_NODES * HID];
__device__ float g_P  [(size_t)NCANDE * 512];
__device__ float g_stats[2 * HID];
// pre-rounded (tf32-representable) weights
__device__ float g_wc1[NLAY * HID * HID];
__device__ float g_wc2[NLAY * HID * HID];
__device__ float g_w1t[512 * 512];      // combined epW1, transposed [N=512][K=512]
__device__ float g_w2 [256 * 128];
// CSR scratch
__device__ int g_deg[N_NODES];
__device__ int g_off[N_NODES + 1];
__device__ int g_pos[N_NODES];
__device__ int g_csr[N_EDGES];
__device__ int g_bsum[128];

// ------------------------------- small utils --------------------------------
__global__ void zeroi_kernel(int* p, int n) {
    int i = blockIdx.x * blockDim.x + threadIdx.x;
    if (i < n) p[i] = 0;
}

// ----------------------------- tf32 helpers ----------------------------------
__device__ __forceinline__ unsigned f2tf32(float f) {
    unsigned r;
    asm("cvt.rna.tf32.f32 %0, %1;" : "=r"(r) : "f"(f));
    return r;
}
__device__ __forceinline__ float rtf(float f) { return __uint_as_float(f2tf32(f)); }
__device__ __forceinline__ uint4 cvt4(float4 v) {
    uint4 w;
    w.x = f2tf32(v.x); w.y = f2tf32(v.y); w.z = f2tf32(v.z); w.w = f2tf32(v.w);
    return w;
}
__device__ __forceinline__ void mma8(float* d, unsigned a0, unsigned a1, unsigned a2,
                                     unsigned a3, unsigned b0, unsigned b1) {
    asm volatile(
        "mma.sync.aligned.m16n8k8.row.col.f32.tf32.tf32.f32 "
        "{%0,%1,%2,%3}, {%4,%5,%6,%7}, {%8,%9}, {%0,%1,%2,%3};"
        : "+f"(d[0]), "+f"(d[1]), "+f"(d[2]), "+f"(d[3])
        : "r"(a0), "r"(a1), "r"(a2), "r"(a3), "r"(b0), "r"(b1));
}
__device__ __forceinline__ void cp16(unsigned sdst, const void* gsrc, int srcbytes) {
    asm volatile("cp.async.ca.shared.global [%0], [%1], 16, %2;"
                 :: "r"(sdst), "l"(gsrc), "r"(srcbytes));
}
#define CP_COMMIT() asm volatile("cp.async.commit_group;")
#define CP_WAIT0()  asm volatile("cp.async.wait_group 0;" ::: "memory")

// ldmatrix: reg i = matrix i; lane l gets word (row l>>2, chunk l&3) of each.
__device__ __forceinline__ void ldsm4(unsigned& r0, unsigned& r1, unsigned& r2,
                                      unsigned& r3, uint32_t addr) {
    asm volatile("ldmatrix.sync.aligned.m8n8.x4.shared.b16 {%0,%1,%2,%3}, [%4];"
                 : "=r"(r0), "=r"(r1), "=r"(r2), "=r"(r3) : "r"(addr));
}

// round weights once (makes HW tf32 truncation exact == cvt.rna semantics)
__global__ void round_weights_kernel(const float* __restrict__ cW1,
                                     const float* __restrict__ cW2,
                                     const float* __restrict__ epW2,
                                     float* __restrict__ wc1, float* __restrict__ wc2,
                                     float* __restrict__ w2) {
    int i = blockIdx.x * blockDim.x + threadIdx.x;
    if (i < NLAY * HID * HID) { wc1[i] = rtf(cW1[i]); wc2[i] = rtf(cW2[i]); }
    if (i < 256 * 128)  w2[i] = rtf(epW2[i]);
}

// build combined transposed [N=512][K=512] epW1 (halves side by side in N)
__global__ void build_w1t_kernel(const float* __restrict__ epW1, float* __restrict__ w1t) {
    int i = blockIdx.x * blockDim.x + threadIdx.x;   // i = n*512 + k
    if (i >= 512 * 512) return;
    int n = i >> 9, k = i & 511;
    float v = (n < 256) ? epW1[(size_t)k * 256 + n]
                        : epW1[(size_t)(512 + k) * 256 + (n - 256)];
    w1t[i] = rtf(v);
}

// ------------------------------ CSR build ------------------------------------
__global__ void hist_kernel(const int* __restrict__ ei, int* __restrict__ deg) {
    int e = blockIdx.x * blockDim.x + threadIdx.x;
    if (e < N_EDGES) atomicAdd(&deg[ei[N_EDGES + e]], 1);
}

#define SCAN_B 1024
__global__ void scan_block_kernel(const int* __restrict__ deg, int* __restrict__ off,
                                  int* __restrict__ bsum, int n) {
    __shared__ int sh[SCAN_B];
    int g = blockIdx.x * SCAN_B + threadIdx.x;
    int v = (g < n) ? deg[g] : 0;
    sh[threadIdx.x] = v;
    __syncthreads();
#pragma unroll
    for (int o = 1; o < SCAN_B; o <<= 1) {
        int t = (threadIdx.x >= o) ? sh[threadIdx.x - o] : 0;
        __syncthreads();
        sh[threadIdx.x] += t;
        __syncthreads();
    }
    if (g < n) off[g] = sh[threadIdx.x] - v;
    if (threadIdx.x == SCAN_B - 1) bsum[blockIdx.x] = sh[SCAN_B - 1];
}

__global__ void scan_bsum_kernel(int* __restrict__ bsum, int nb) {
    __shared__ int sh[128];
    int v = (threadIdx.x < nb) ? bsum[threadIdx.x] : 0;
    sh[threadIdx.x] = v;
    __syncthreads();
#pragma unroll
    for (int o = 1; o < 128; o <<= 1) {
        int t = (threadIdx.x >= o) ? sh[threadIdx.x - o] : 0;
        __syncthreads();
        sh[threadIdx.x] += t;
        __syncthreads();
    }
    if (threadIdx.x < nb) bsum[threadIdx.x] = sh[threadIdx.x] - v;
}

__global__ void scan_add_kernel(int* __restrict__ off, const int* __restrict__ bsum,
                                int* __restrict__ pos, int n) {
    int g = blockIdx.x * blockDim.x + threadIdx.x;
    if (g < n) {
        int o = off[g] + bsum[g / SCAN_B];
        off[g] = o;
        pos[g] = o;
    }
    if (g == n) off[n] = N_EDGES;
}

__global__ void csr_fill_kernel(const int* __restrict__ ei, int* __restrict__ pos,
                                int* __restrict__ csr) {
    int e = blockIdx.x * blockDim.x + threadIdx.x;
    if (e >= N_EDGES) return;
    int dst = ei[N_EDGES + e];
    int p = atomicAdd(&pos[dst], 1);
    csr[p] = ei[e];
}

// --------- GIN aggregation: warp-per-node gather (+ zero stats by block 0) ----
__global__ void gin_gather_kernel(const int* __restrict__ off,
                                  const int* __restrict__ csr,
                                  const float* __restrict__ h, int hstride,
                                  const float* __restrict__ ceps, int layer,
                                  float* __restrict__ agg,
                                  float* __restrict__ stats) {
    if (blockIdx.x == 0 && threadIdx.x < 2 * HID) stats[threadIdx.x] = 0.f;
    int node = (blockIdx.x * blockDim.x + threadIdx.x) >> 5;
    int lane = threadIdx.x & 31;
    if (node >= N_NODES) return;
    int s = off[node], e = off[node + 1];
    float c = 1.f + __ldg(&ceps[layer]);
    float4 acc = __ldg((const float4*)(h + (size_t)node * hstride) + lane);
    acc.x *= c; acc.y *= c; acc.z *= c; acc.w *= c;
    for (int i = s; i < e; i++) {
        int src = __ldg(&csr[i]);
        float4 v = __ldg((const float4*)(h + (size_t)src * hstride) + lane);
        acc.x += v.x; acc.y += v.y; acc.z += v.z; acc.w += v.w;
    }
    acc.x = rtf(acc.x); acc.y = rtf(acc.y); acc.z = rtf(acc.z); acc.w = rtf(acc.w);
    *((float4*)(agg + (size_t)node * HID) + lane) = acc;
}

#define SA  36
#define SZ  132
#define SW  136
#define SB  136
#define SBT 36
#define GIN_SMEM ((128 * SZ + 32 * SW) * 4)                 // 84992 B -> 2 CTA/SM
#define WIDE_SMEM ((2 * 128 * SA + 2 * 256 * SBT) * 4)      // 110592 B

// ---- GEMM phase: A persistent in smem (128xSZ), weight chunks reg-prefetched --
__device__ __forceinline__ void gemm128(const unsigned* __restrict__ z1s,
                                        unsigned* __restrict__ Ws,
                                        const float* __restrict__ W,
                                        float acc[4][4][4],
                                        int tid, int warpM, int warpN,
                                        int gid, int tig) {
#pragma unroll
    for (int a = 0; a < 4; a++)
#pragma unroll
        for (int b = 0; b < 4; b++)
#pragma unroll
            for (int c = 0; c < 4; c++) acc[a][b][c] = 0.f;

    int wr = tid >> 5, wcq = (tid & 31) << 2;
    float4 pre[4];
#pragma unroll
    for (int i = 0; i < 4; i++)
        pre[i] = __ldg((const float4*)(W + (size_t)(wr + i * 8) * HID + wcq));

    for (int k0 = 0; k0 < 128; k0 += 32) {
#pragma unroll
        for (int i = 0; i < 4; i++)
            *(uint4*)(Ws + (wr + i * 8) * SW + wcq) = cvt4(pre[i]);
        __syncthreads();
        if (k0 < 96) {
#pragma unroll
            for (int i = 0; i < 4; i++)
                pre[i] = __ldg((const float4*)(W + (size_t)(k0 + 32 + wr + i * 8) * HID + wcq));
        }
#pragma unroll
        for (int ks = 0; ks < 32; ks += 8) {
            unsigned af[4][4], bf[4][2];
#pragma unroll
            for (int mt = 0; mt < 4; mt++) {
                const unsigned* p = z1s + (warpM + mt * 16 + gid) * SZ + k0 + ks + tig;
                af[mt][0] = p[0];
                af[mt][1] = p[8 * SZ];
                af[mt][2] = p[4];
                af[mt][3] = p[8 * SZ + 4];
            }
#pragma unroll
            for (int nt = 0; nt < 4; nt++) {
                const unsigned* p = Ws + (ks + tig) * SW + warpN + nt * 8 + gid;
                bf[nt][0] = p[0];
                bf[nt][1] = p[4 * SW];
            }
#pragma unroll
            for (int mt = 0; mt < 4; mt++)
#pragma unroll
                for (int nt = 0; nt < 4; nt++)
                    mma8(acc[mt][nt], af[mt][0], af[mt][1], af[mt][2], af[mt][3],
                         bf[nt][0], bf[nt][1]);
        }
        __syncthreads();
    }
}

// ---- fused node-layer MLP: z2 = relu(relu(agg@W1+b1)@W2+b2), + BN stats ----
__global__ __launch_bounds__(256, 2)
void gin_mlp_kernel(const float* __restrict__ agg,
                    const float* __restrict__ W1, const float* __restrict__ b1,
                    const float* __restrict__ W2, const float* __restrict__ b2,
                    float* __restrict__ z2out, float* __restrict__ stats) {
    extern __shared__ unsigned dsm[];
    unsigned* z1s = dsm;
    unsigned* Ws  = dsm + 128 * SZ;
    int tid = threadIdx.x;
    int warp = tid >> 5, lane = tid & 31;
    int gid = lane >> 2, tig = lane & 3;
    int row0 = blockIdx.x * 128;
    int warpM = (warp >> 2) * 64;
    int warpN = (warp & 3) * 32;

    {
        unsigned sZ = (unsigned)__cvta_generic_to_shared(z1s);
        int r = tid >> 1, cb = (tid & 1) * 64;
        int gr = row0 + r;
        int ok = (gr < N_NODES) ? 16 : 0;
        const float* src = agg + (size_t)(ok ? gr : 0) * HID + cb;
#pragma unroll
        for (int c = 0; c < 16; c++)
            cp16(sZ + (unsigned)(r * SZ + cb + c * 4) * 4u, src + c * 4, ok);
        CP_COMMIT();
        CP_WAIT0();
    }
    __syncthreads();

    float acc[4][4][4];

    gemm128(z1s, Ws, W1, acc, tid, warpM, warpN, gid, tig);
#pragma unroll
    for (int mt = 0; mt < 4; mt++)
#pragma unroll
        for (int half = 0; half < 2; half++) {
            int r = warpM + mt * 16 + gid + half * 8;
#pragma unroll
            for (int nt = 0; nt < 4; nt++) {
                int gc = warpN + nt * 8 + tig * 2;
                float vx = fmaxf(acc[mt][nt][half * 2 + 0] + __ldg(&b1[gc]), 0.f);
                float vy = fmaxf(acc[mt][nt][half * 2 + 1] + __ldg(&b1[gc + 1]), 0.f);
                z1s[r * SZ + gc]     = f2tf32(vx);
                z1s[r * SZ + gc + 1] = f2tf32(vy);
            }
        }
    __syncthreads();

    gemm128(z1s, Ws, W2, acc, tid, warpM, warpN, gid, tig);

    float* sS = (float*)Ws;
    float* sQ = sS + 128;
    if (tid < 256) ((float*)Ws)[tid] = 0.f;
    __syncthreads();

    float sumS[4][2] = {}, sumQ[4][2] = {};
#pragma unroll
    for (int mt = 0; mt < 4; mt++)
#pragma unroll
        for (int half = 0; half < 2; half++) {
            int gr = row0 + warpM + mt * 16 + gid + half * 8;
            if (gr >= N_NODES) continue;
#pragma unroll
            for (int nt = 0; nt < 4; nt++) {
                int gc = warpN + nt * 8 + tig * 2;
                float vx = fmaxf(acc[mt][nt][half * 2 + 0] + __ldg(&b2[gc]), 0.f);
                float vy = fmaxf(acc[mt][nt][half * 2 + 1] + __ldg(&b2[gc + 1]), 0.f);
                *(float2*)(z2out + (size_t)gr * HID + gc) = make_float2(vx, vy);
                sumS[nt][0] += vx; sumQ[nt][0] += vx * vx;
                sumS[nt][1] += vy; sumQ[nt][1] += vy * vy;
            }
        }
#pragma unroll
    for (int nt = 0; nt < 4; nt++) {
        int gc = warpN + nt * 8 + tig * 2;
        atomicAdd(&sS[gc],     sumS[nt][0]);
        atomicAdd(&sS[gc + 1], sumS[nt][1]);
        atomicAdd(&sQ[gc],     sumQ[nt][0]);
        atomicAdd(&sQ[gc + 1], sumQ[nt][1]);
    }
    __syncthreads();
    if (tid < 128) {
        atomicAdd(&stats[tid],       sS[tid]);
        atomicAdd(&stats[HID + tid], sQ[tid]);
    }
}

// ------- WIDE P-GEMM with ldmatrix (coalesced staging): 128x256, K=512 -------
__global__ __launch_bounds__(256, 1)
void tf32_gemm_wide(const float* __restrict__ A, int lda,
                    const float* __restrict__ Bt,
                    float* __restrict__ C, int ldc, int M) {
    extern __shared__ float sm[];
    float* Ab[2] = { sm, sm + 128 * SA };
    float* Bb[2] = { sm + 2 * 128 * SA, sm + 2 * 128 * SA + 256 * SBT };
    int tid = threadIdx.x;
    int warp = tid >> 5, lane = tid & 31;
    int row0 = blockIdx.y * 128;
    int col0 = blockIdx.x * 256;
    int warpM = (warp >> 2) * 64;
    int warpN = (warp & 3) * 64;

    int ar = tid >> 3, acq = (tid & 7) << 2;

    int a_row = lane & 15, a_koff = (lane >> 4) * 4;
    int b_row = lane & 7, b_koff = ((lane >> 3) & 1) * 4;
    int b_nsel = (lane >> 4);

    float acc[4][8][4];
#pragma unroll
    for (int a = 0; a < 4; a++)
#pragma unroll
        for (int b = 0; b < 8; b++)
#pragma unroll
            for (int c = 0; c < 4; c++) acc[a][b][c] = 0.f;

    {
        unsigned sA = (unsigned)__cvta_generic_to_shared(Ab[0]);
        unsigned sB = (unsigned)__cvta_generic_to_shared(Bb[0]);
#pragma unroll
        for (int i = 0; i < 4; i++) {
            int r = ar + i * 32;
            int gr = row0 + r;
            int ok = (gr < M) ? 16 : 0;
            cp16(sA + (unsigned)(r * SA + acq) * 4u,
                 A + (size_t)(ok ? gr : 0) * lda + acq, ok);
        }
#pragma unroll
        for (int i = 0; i < 8; i++) {
            int f = tid + i * 256;
            int r = f >> 3, c = (f & 7) << 2;
            cp16(sB + (unsigned)(r * SBT + c) * 4u,
                 Bt + (size_t)(col0 + r) * 512 + c, 16);
        }
        CP_COMMIT();
    }

    for (int t = 0; t < 16; t++) {
        CP_WAIT0();
        __syncthreads();
        if (t + 1 < 16) {
            int nb = (t + 1) & 1;
            int k0 = (t + 1) << 5;
            unsigned sA = (unsigned)__cvta_generic_to_shared(Ab[nb]);
            unsigned sB = (unsigned)__cvta_generic_to_shared(Bb[nb]);
#pragma unroll
            for (int i = 0; i < 4; i++) {
                int r = ar + i * 32;
                int gr = row0 + r;
                int ok = (gr < M) ? 16 : 0;
                cp16(sA + (unsigned)(r * SA + acq) * 4u,
                     A + (size_t)(ok ? gr : 0) * lda + k0 + acq, ok);
            }
#pragma unroll
            for (int i = 0; i < 8; i++) {
                int f = tid + i * 256;
                int r = f >> 3, c = (f & 7) << 2;
                cp16(sB + (unsigned)(r * SBT + c) * 4u,
                     Bt + (size_t)(col0 + r) * 512 + k0 + c, 16);
            }
            CP_COMMIT();
        }
        unsigned aBase = (unsigned)__cvta_generic_to_shared(Ab[t & 1]);
        unsigned bBase = (unsigned)__cvta_generic_to_shared(Bb[t & 1]);
#pragma unroll
        for (int ks = 0; ks < 32; ks += 8) {
            unsigned af[4][4], bf[8][2];
#pragma unroll
            for (int mt = 0; mt < 4; mt++) {
                uint32_t addr = aBase +
                    (unsigned)((warpM + mt * 16 + a_row) * SA + ks + a_koff) * 4u;
                ldsm4(af[mt][0], af[mt][1], af[mt][2], af[mt][3], addr);
            }
#pragma unroll
            for (int j = 0; j < 4; j++) {
                uint32_t addr = bBase +
                    (unsigned)((warpN + (2 * j + b_nsel) * 8 + b_row) * SBT
                               + ks + b_koff) * 4u;
                ldsm4(bf[2 * j][0], bf[2 * j][1], bf[2 * j + 1][0], bf[2 * j + 1][1],
                      addr);
            }
#pragma unroll
            for (int mt = 0; mt < 4; mt++)
#pragma unroll
                for (int nt = 0; nt < 8; nt++)
                    mma8(acc[mt][nt], af[mt][0], af[mt][1], af[mt][2], af[mt][3],
                         bf[nt][0], bf[nt][1]);
        }
    }

    int gid = lane >> 2, tig = lane & 3;
#pragma unroll
    for (int mt = 0; mt < 4; mt++) {
#pragma unroll
        for (int half = 0; half < 2; half++) {
            int gr = row0 + warpM + mt * 16 + gid + half * 8;
            if (gr >= M) continue;
#pragma unroll
            for (int nt = 0; nt < 8; nt++) {
                int gc = col0 + warpN + nt * 8 + tig * 2;
                float2 v;
                v.x = acc[mt][nt][half * 2 + 0];
                v.y = acc[mt][nt][half * 2 + 1];
                *(float2*)(C + (size_t)gr * ldc + gc) = v;
            }
        }
    }
}

// -- fused edge kernel: gather + GEMM(K=256) + score dot + smem reduce+sigmoid --
__global__ __launch_bounds__(256, 2)
void ep_fused_kernel(const int* __restrict__ ce,
                     const float* __restrict__ P,
                     const float* __restrict__ b1,
                     const float* __restrict__ W2,
                     const float* __restrict__ b2,
                     const float* __restrict__ w3,
                     const float* __restrict__ b3,
                     float* __restrict__ score) {
    __shared__ unsigned As[128 * SA];
    __shared__ unsigned Bs[32 * SB];
    int tid = threadIdx.x;
    int warp = tid >> 5, lane = tid & 31;
    int gid = lane >> 2, tig = lane & 3;
    int row0 = blockIdx.x * 128;
    int warpM = (warp >> 2) * 64;
    int warpN = (warp & 3) * 32;

    int rloc[4], c0v[4], c1v[4], cqv[4];
#pragma unroll
    for (int i = 0; i < 4; i++) {
        int f = tid + i * 256;
        rloc[i] = f >> 3;
        cqv[i] = (f & 7) << 2;
        int gr = row0 + rloc[i];
        if (gr < NCANDE) {
            c0v[i] = __ldg(&ce[gr]);
            c1v[i] = __ldg(&ce[NCANDE + gr]);
        } else { c0v[i] = 0; c1v[i] = 0; }
    }

    float acc[4][4][4];
#pragma unroll
    for (int a = 0; a < 4; a++)
#pragma unroll
        for (int b = 0; b < 4; b++)
#pragma unroll
            for (int c = 0; c < 4; c++) acc[a][b][c] = 0.f;

    for (int k0 = 0; k0 < 256; k0 += 32) {
#pragma unroll
        for (int i = 0; i < 4; i++) {
            int r = rloc[i], cq = cqv[i];
            float4 v = make_float4(0.f, 0.f, 0.f, 0.f);
            if (row0 + r < NCANDE) {
                float4 a = __ldg((const float4*)(P + (size_t)c0v[i] * 512 + k0 + cq));
                float4 b = __ldg((const float4*)(P + (size_t)c1v[i] * 512 + 256 + k0 + cq));
                float4 bb = __ldg((const float4*)(b1 + k0 + cq));
                v.x = fmaxf(a.x + b.x + bb.x, 0.f);
                v.y = fmaxf(a.y + b.y + bb.y, 0.f);
                v.z = fmaxf(a.z + b.z + bb.z, 0.f);
                v.w = fmaxf(a.w + b.w + bb.w, 0.f);
            }
            *(uint4*)(As + r * SA + cq) = cvt4(v);
        }
#pragma unroll
        for (int i = 0; i < 4; i++) {
            int f = tid + i * 256;
            int r = f >> 5, cq = (f & 31) << 2;
            float4 v = __ldg((const float4*)(W2 + (size_t)(k0 + r) * HID + cq));
            *(uint4*)(Bs + r * SB + cq) =
                make_uint4(__float_as_uint(v.x), __float_as_uint(v.y),
                           __float_as_uint(v.z), __float_as_uint(v.w));
        }
        __syncthreads();
#pragma unroll
        for (int ks = 0; ks < 32; ks += 8) {
            unsigned af[4][4], bf[4][2];
#pragma unroll
            for (int mt = 0; mt < 4; mt++) {
                const unsigned* p = As + (warpM + mt * 16 + gid) * SA + ks + tig;
                af[mt][0] = p[0];
                af[mt][1] = p[8 * SA];
                af[mt][2] = p[4];
                af[mt][3] = p[8 * SA + 4];
            }
#pragma unroll
            for (int nt = 0; nt < 4; nt++) {
                const unsigned* p = Bs + (ks + tig) * SB + warpN + nt * 8 + gid;
                bf[nt][0] = p[0];
                bf[nt][1] = p[4 * SB];
            }
#pragma unroll
            for (int mt = 0; mt < 4; mt++)
#pragma unroll
                for (int nt = 0; nt < 4; nt++)
                    mma8(acc[mt][nt], af[mt][0], af[mt][1], af[mt][2], af[mt][3],
                         bf[nt][0], bf[nt][1]);
        }
        __syncthreads();
    }

    float* sSc = (float*)As;
    if (tid < 128) sSc[tid] = 0.f;
    __syncthreads();
#pragma unroll
    for (int mt = 0; mt < 4; mt++)
#pragma unroll
        for (int half = 0; half < 2; half++) {
            int r = warpM + mt * 16 + gid + half * 8;
            float p = 0.f;
#pragma unroll
            for (int nt = 0; nt < 4; nt++) {
                int gc = warpN + nt * 8 + tig * 2;
                float vx = fmaxf(acc[mt][nt][half * 2 + 0] + __ldg(&b2[gc]), 0.f);
                float vy = fmaxf(acc[mt][nt][half * 2 + 1] + __ldg(&b2[gc + 1]), 0.f);
                p = fmaf(vx, __ldg(&w3[gc]), p);
                p = fmaf(vy, __ldg(&w3[gc + 1]), p);
            }
            p += __shfl_xor_sync(0xffffffffu, p, 1);
            p += __shfl_xor_sync(0xffffffffu, p, 2);
            if (tig == 0) atomicAdd(&sSc[r], p);
        }
    __syncthreads();
    if (tid < 128) {
        int gr = row0 + tid;
        if (gr < NCANDE) {
            float z = sSc[tid] + __ldg(&b3[0]);
            score[gr] = 1.f / (1.f + expf(-z));
        }
    }
}

// ------------------------------ batch norm apply ------------------------------
__global__ void bn_apply_kernel(const float* __restrict__ Z,
                                const float* __restrict__ stats,
                                const float* __restrict__ gamma,
                                const float* __restrict__ beta,
                                float* __restrict__ out, int ostride) {
    int idx = blockIdx.x * blockDim.x + threadIdx.x;
    if (idx >= N_NODES * HID) return;
    int row = idx / HID, col = idx - row * HID;
    float inv_n = 1.f / (float)N_NODES;
    float mu = stats[col] * inv_n;
    float var = stats[HID + col] * inv_n - mu * mu;
    float scale = rsqrtf(var + BN_EPSF) * gamma[col];
    out[(size_t)row * ostride + col] = rtf((Z[idx] - mu) * scale + beta[col]);
}

// ------ fused classifier: per-graph mean pool + 4-layer MLP + log-softmax -----
__global__ __launch_bounds__(256, 4)
void classifier_kernel(const float* __restrict__ emb,
                       const int* __restrict__ batch,
                       const float* __restrict__ W1, const float* __restrict__ b1,
                       const float* __restrict__ W2, const float* __restrict__ b2,
                       const float* __restrict__ W3, const float* __restrict__ b3,
                       const float* __restrict__ W4, const float* __restrict__ b4,
                       float* __restrict__ out) {
    __shared__ float sg[EMBW];
    __shared__ float st1[256];
    __shared__ float st2[128];
    __shared__ float st3[128];
    __shared__ float slg[NCLS];
    int g = blockIdx.x;
    int tid = threadIdx.x;

    int lo = 0, hi = N_NODES;
    while (lo < hi) { int m = (lo + hi) >> 1; if (batch[m] < g) lo = m + 1; else hi = m; }
    int s0 = lo;
    lo = s0; hi = N_NODES;
    while (lo < hi) { int m = (lo + hi) >> 1; if (batch[m] < g + 1) lo = m + 1; else hi = m; }
    int s1 = lo;

    float inv = 1.f / fmaxf((float)(s1 - s0), 1.f);
    float a0 = 0.f, a1 = 0.f;
    for (int r = s0; r < s1; r++) {
        a0 += __ldg(emb + (size_t)r * EMBW + tid);
        a1 += __ldg(emb + (size_t)r * EMBW + tid + 256);
    }
    sg[tid]       = a0 * inv;
    sg[tid + 256] = a1 * inv;
    __syncthreads();

    {
        float v = __ldg(&b1[tid]);
        for (int k = 0; k < EMBW; k++) v = fmaf(sg[k], __ldg(&W1[(size_t)k * 256 + tid]), v);
        st1[tid] = fmaxf(v, 0.f);
    }
    __syncthreads();
    if (tid < 128) {
        float v = __ldg(&b2[tid]);
        for (int k = 0; k < 256; k++) v = fmaf(st1[k], __ldg(&W2[(size_t)k * 128 + tid]), v);
        st2[tid] = fmaxf(v, 0.f);
    }
    __syncthreads();
    if (tid < 128) {
        float v = __ldg(&b3[tid]);
        for (int k = 0; k < 128; k++) v = fmaf(st2[k], __ldg(&W3[(size_t)k * 128 + tid]), v);
        st3[tid] = fmaxf(v, 0.f);
    }
    __syncthreads();
    if (tid < NCLS) {
        float v = __ldg(&b4[tid]);
        for (int k = 0; k < 128; k++) v = fmaf(st3[k], __ldg(&W4[(size_t)k * NCLS + tid]), v);
        slg[tid] = v;
    }
    __syncthreads();
    if (tid < 32) {
        float v = (tid < NCLS) ? slg[tid] : -INFINITY;
        float m = v;
#pragma unroll
        for (int o = 16; o > 0; o >>= 1) m = fmaxf(m, __shfl_xor_sync(0xffffffffu, m, o));
        float e = (tid < NCLS) ? expf(v - m) : 0.f;
        float s = e;
#pragma unroll
        for (int o = 16; o > 0; o >>= 1) s += __shfl_xor_sync(0xffffffffu, s, o);
        if (tid < NCLS) out[g * NCLS + tid] = v - m - logf(s);
    }
}

// --------------------------------- host --------------------------------------
static void* sym_addr(const void* sym) {
    void* p = nullptr;
    cudaGetSymbolAddress(&p, sym);
    return p;
}

extern "C" void kernel_launch(void* const* d_in, const int* in_sizes, int n_in,
                              void* d_out, int out_size) {
    (void)n_in; (void)out_size;
    const float *x, *cW1, *cb1, *cW2, *cb2, *cgamma, *cbeta, *ceps;
    const float *ncW1, *ncb1, *ncW2, *ncb2, *ncW3, *ncb3, *ncW4, *ncb4;
    const float *epW1, *epb1, *epW2, *epb2, *epW3, *epb3;
    const int *edge_index, *batch, *cand;
    bool dict_order = (in_sizes[1] == 2 * N_EDGES);
    if (dict_order) {
        x          = (const float*)d_in[0];
        edge_index = (const int*)  d_in[1];
        batch      = (const int*)  d_in[2];
        cand       = (const int*)  d_in[3];
        cW1 = (const float*)d_in[4];  cb1 = (const float*)d_in[5];
        cW2 = (const float*)d_in[6];  cb2 = (const float*)d_in[7];
        cgamma = (const float*)d_in[8]; cbeta = (const float*)d_in[9];
        ceps = (const float*)d_in[10];
        ncW1 = (const float*)d_in[11]; ncb1 = (const float*)d_in[12];
        ncW2 = (const float*)d_in[13]; ncb2 = (const float*)d_in[14];
        ncW3 = (const float*)d_in[15]; ncb3 = (const float*)d_in[16];
        ncW4 = (const float*)d_in[17]; ncb4 = (const float*)d_in[18];
        epW1 = (const float*)d_in[19]; epb1 = (const float*)d_in[20];
        epW2 = (const float*)d_in[21]; epb2 = (const float*)d_in[22];
        epW3 = (const float*)d_in[23]; epb3 = (const float*)d_in[24];
    } else {
        x = (const float*)d_in[0];
        cW1 = (const float*)d_in[1];  cb1 = (const float*)d_in[2];
        cW2 = (const float*)d_in[3];  cb2 = (const float*)d_in[4];
        cgamma = (const float*)d_in[5]; cbeta = (const float*)d_in[6];
        ceps = (const float*)d_in[7];
        ncW1 = (const float*)d_in[8];  ncb1 = (const float*)d_in[9];
        ncW2 = (const float*)d_in[10]; ncb2 = (const float*)d_in[11];
        ncW3 = (const float*)d_in[12]; ncb3 = (const float*)d_in[13];
        ncW4 = (const float*)d_in[14]; ncb4 = (const float*)d_in[15];
        epW1 = (const float*)d_in[16]; epb1 = (const float*)d_in[17];
        epW2 = (const float*)d_in[18]; epb2 = (const float*)d_in[19];
        epW3 = (const float*)d_in[20]; epb3 = (const float*)d_in[21];
        edge_index = (const int*)d_in[22];
        batch      = (const int*)d_in[23];
        cand       = (const int*)d_in[24];
    }
    float* out = (float*)d_out;

    float* p_emb  = (float*)sym_addr(g_emb);
    float* p_agg  = (float*)sym_addr(g_agg);
    float* p_z2   = (float*)sym_addr(g_z2);
    float* p_P    = (float*)sym_addr(g_P);
    float* p_st   = (float*)sym_addr(g_stats);
    float* p_wc1  = (float*)sym_addr(g_wc1);
    float* p_wc2  = (float*)sym_addr(g_wc2);
    float* p_w1t  = (float*)sym_addr(g_w1t);
    float* p_w2   = (float*)sym_addr(g_w2);
    int* p_deg  = (int*)sym_addr(g_deg);
    int* p_off  = (int*)sym_addr(g_off);
    int* p_pos  = (int*)sym_addr(g_pos);
    int* p_csr  = (int*)sym_addr(g_csr);
    int* p_bsum = (int*)sym_addr(g_bsum);

    static cudaStream_t s2 = nullptr;
    static cudaEvent_t evA = nullptr, evB = nullptr, evC = nullptr, evD = nullptr;
    static bool attr_done = false;
    if (!attr_done) {
        cudaFuncSetAttribute(gin_mlp_kernel,
                             cudaFuncAttributeMaxDynamicSharedMemorySize, GIN_SMEM);
        cudaFuncSetAttribute(tf32_gemm_wide,
                             cudaFuncAttributeMaxDynamicSharedMemorySize, WIDE_SMEM);
        cudaStreamCreateWithFlags(&s2, cudaStreamNonBlocking);
        cudaEventCreateWithFlags(&evA, cudaEventDisableTiming);
        cudaEventCreateWithFlags(&evB, cudaEventDisableTiming);
        cudaEventCreateWithFlags(&evC, cudaEventDisableTiming);
        cudaEventCreateWithFlags(&evD, cudaEventDisableTiming);
        attr_done = true;
    }

    const int T = 256;
    const int NODE_BLKS = (N_NODES + 127) / 128;
    const int CAND_BLKS = (NCANDE + 127) / 128;
    const int nScanBlocks = (N_NODES + SCAN_B - 1) / SCAN_B;

    // ===== fork 1: CSR build on s2, weight prep on main =====
    cudaEventRecord(evA, 0);
    cudaStreamWaitEvent(s2, evA, 0);
    zeroi_kernel<<<(N_NODES + T - 1) / T, T, 0, s2>>>(p_deg, N_NODES);
    hist_kernel<<<(N_EDGES + T - 1) / T, T, 0, s2>>>(edge_index, p_deg);
    scan_block_kernel<<<nScanBlocks, SCAN_B, 0, s2>>>(p_deg, p_off, p_bsum, N_NODES);
    scan_bsum_kernel<<<1, 128, 0, s2>>>(p_bsum, nScanBlocks);
    scan_add_kernel<<<(N_NODES + T) / T, T, 0, s2>>>(p_off, p_bsum, p_pos, N_NODES);
    csr_fill_kernel<<<(N_EDGES + T - 1) / T, T, 0, s2>>>(edge_index, p_pos, p_csr);
    cudaEventRecord(evB, s2);

    round_weights_kernel<<<(NLAY * HID * HID + T - 1) / T, T>>>(cW1, cW2, epW2,
                                                                p_wc1, p_wc2, p_w2);
    build_w1t_kernel<<<(512 * 512 + T - 1) / T, T>>>(epW1, p_w1t);
    cudaStreamWaitEvent(0, evB, 0);     // join CSR before gathers

    // ================= GIN layers =================
    for (int l = 0; l < NLAY; l++) {
        const float* h = (l == 0) ? x : (p_emb + (l - 1) * HID);
        int hstride = (l == 0) ? HID : EMBW;

        gin_gather_kernel<<<(N_NODES * 32 + T - 1) / T, T>>>(p_off, p_csr, h, hstride,
                                                             ceps, l, p_agg, p_st);
        gin_mlp_kernel<<<NODE_BLKS, 256, GIN_SMEM>>>(
            p_agg,
            p_wc1 + (size_t)l * HID * HID, cb1 + l * HID,
            p_wc2 + (size_t)l * HID * HID, cb2 + l * HID,
            p_z2, p_st);
        bn_apply_kernel<<<(N_NODES * HID + T - 1) / T, T>>>(
            p_z2, p_st, cgamma + l * HID, cbeta + l * HID, p_emb + l * HID, EMBW);
    }

    // ===== fork 2: classifier on s2 overlapped with edge predictor on main =====
    cudaEventRecord(evC, 0);
    cudaStreamWaitEvent(s2, evC, 0);
    classifier_kernel<<<N_GRAPH, 256, 0, s2>>>(p_emb, batch,
                                               ncW1, ncb1, ncW2, ncb2,
                                               ncW3, ncb3, ncW4, ncb4, out);
    cudaEventRecord(evD, s2);

    {
        dim3 wg(2, NODE_BLKS);
        tf32_gemm_wide<<<wg, 256, WIDE_SMEM>>>(p_emb, EMBW, p_w1t, p_P, 512, N_NODES);
    }
    float* scores = out + N_GRAPH * NCLS;
    ep_fused_kernel<<<CAND_BLKS, 256>>>(cand, p_P, epb1, p_w2, epb2, epW3, epb3, scores);
    cudaStreamWaitEvent(0, evD, 0);     // join classifier before graph end
}